// round 11
// baseline (speedup 1.0000x reference)
#include <cuda_runtime.h>
#include <cuda_fp16.h>
#include <math.h>
#include <cstdint>

#define N_NODES 51200
#define N_EDGES 819200
#define NG 512
#define NPG 100
#define EPG 1600
#define HID 512
#define FIN 128
#define EPSV 1e-5f

#define OUT_LOGP 0
#define OUT_POS 3072
#define OUT_GEMB 265216
#define OUT_PEN 527360

// ---------------- scratch (static device allocations; no cudaMalloc) --------
__device__ __half d_Ah[NG * 128 * 120];        // padded half adjacency [g][m:128][k:120]
__device__ __half d_Th[N_NODES * HID];         // GEMM output (half)
__device__ __half d_Hh[N_NODES * HID];         // agg output (half)
__device__ __half d_Xh[N_NODES * FIN];         // x in half
__device__ __half d_Wh[4][HID * HID];          // transposed half weights [N][K]
__device__ float d_T[N_NODES * HID];           // fp32 scratch (head path)
__device__ float d_araw[N_NODES * 2];          // raw assignment logits (atomic acc)
__device__ float d_assign[N_NODES * 2];
__device__ float d_pos[NG * HID];
__device__ float d_gvec[HID];
__device__ float d_scal[4];                    // [0]=pos ss, [1]=pg ms, [2]=penalty acc

// ---------------- ptx helpers ----------------------------------------------
__device__ __forceinline__ uint32_t s2u(const void* p) {
    uint32_t a;
    asm("{ .reg .u64 t; cvta.to.shared.u64 t, %1; cvt.u32.u64 %0, t; }"
        : "=r"(a) : "l"(p));
    return a;
}
__device__ __forceinline__ void cp16(uint32_t s, const void* g) {
    asm volatile("cp.async.cg.shared.global [%0], [%1], 16;" :: "r"(s), "l"(g));
}
__device__ __forceinline__ void mma_f16(float* c, const uint32_t* a, const uint32_t* b) {
    asm volatile(
        "mma.sync.aligned.m16n8k16.row.col.f32.f16.f16.f32 "
        "{%0,%1,%2,%3}, {%4,%5,%6,%7}, {%8,%9}, {%0,%1,%2,%3};"
        : "+f"(c[0]), "+f"(c[1]), "+f"(c[2]), "+f"(c[3])
        : "r"(a[0]), "r"(a[1]), "r"(a[2]), "r"(a[3]), "r"(b[0]), "r"(b[1]));
}
__device__ __forceinline__ void ldm4(uint32_t* r, uint32_t addr) {
    asm volatile("ldmatrix.sync.aligned.m8n8.x4.shared.b16 {%0,%1,%2,%3}, [%4];"
                 : "=r"(r[0]), "=r"(r[1]), "=r"(r[2]), "=r"(r[3]) : "r"(addr));
}
__device__ __forceinline__ void ldm4t(uint32_t* r, uint32_t addr) {
    asm volatile("ldmatrix.sync.aligned.m8n8.x4.trans.shared.b16 {%0,%1,%2,%3}, [%4];"
                 : "=r"(r[0]), "=r"(r[1]), "=r"(r[2]), "=r"(r[3]) : "r"(addr));
}

// ---------------- fused per-graph structure build ---------------------------
__global__ void __launch_bounds__(256) k_build(const int* __restrict__ ei) {
    __shared__ float Adj[NPG * NPG];
    __shared__ float deg[NPG];
    __shared__ float dis[NPG];
    int g = blockIdx.x, tid = threadIdx.x;
    for (int i = tid; i < NPG * NPG; i += 256) Adj[i] = 0.f;
    if (tid < NPG) deg[tid] = 0.f;
    __syncthreads();
    const int* src = ei + g * EPG;
    const int* dst = ei + N_EDGES + g * EPG;
    int base = g * NPG;
    for (int e = tid; e < EPG; e += 256) atomicAdd(&deg[dst[e] - base], 1.f);
    __syncthreads();
    if (tid < NPG) dis[tid] = rsqrtf(deg[tid] + 1.f);
    __syncthreads();
    for (int e = tid; e < EPG; e += 256) {
        int s = src[e] - base, d = dst[e] - base;
        atomicAdd(&Adj[d * NPG + s], dis[s] * dis[d]);
    }
    __syncthreads();
    if (tid < NPG) Adj[tid * NPG + tid] += dis[tid] * dis[tid];
    __syncthreads();
    __half2* out = (__half2*)(d_Ah + (size_t)g * 128 * 120);
    for (int i = tid; i < 128 * 60; i += 256) {
        int r = i / 60, k = (i % 60) * 2;
        float v0 = (r < NPG && k < NPG) ? Adj[r * NPG + k] : 0.f;
        float v1 = (r < NPG && k + 1 < NPG) ? Adj[r * NPG + k + 1] : 0.f;
        out[i] = __floats2half2_rn(v0, v1);
    }
}

__global__ void k_zero_misc() {   // grid 100 x 1024
    int i = blockIdx.x * 1024 + threadIdx.x;
    if (i < N_NODES * 2) d_araw[i] = 0.f;
    if (i < HID) d_gvec[i] = 0.f;
    if (i < 4) d_scal[i] = 0.f;
}

// ---------------- all 4 weight transposes in one launch ---------------------
__global__ void k_transpose_all(const float* __restrict__ W1,
                                const float* __restrict__ W2,
                                const float* __restrict__ W3,
                                const float* __restrict__ Wc1) {
    __shared__ float tile[32][33];
    int z = blockIdx.z;
    const float* W = (z == 0) ? W1 : (z == 1) ? W2 : (z == 2) ? W3 : Wc1;
    int K = (z == 0) ? FIN : HID;
    int k0 = blockIdx.y * 32, n0 = blockIdx.x * 32;
    if (k0 >= K) return;
    __half* Wt = d_Wh[z];
    int tx = threadIdx.x, ty = threadIdx.y;
    for (int j = ty; j < 32; j += 8) tile[j][tx] = W[(size_t)(k0 + j) * HID + n0 + tx];
    __syncthreads();
    for (int j = ty; j < 32; j += 8)
        Wt[(size_t)(n0 + j) * K + k0 + tx] = __float2half_rn(tile[tx][j]);
}

__global__ void k_x2h(const float2* __restrict__ x, __half2* __restrict__ o) {
    int i = blockIdx.x * blockDim.x + threadIdx.x;
    if (i < N_NODES * FIN / 2) o[i] = __float22half2_rn(x[i]);
}

// ---------------- fp16 mma GEMM: C[M,512] = A[M,K] @ Wt[512,K]^T ------------
// 256x128 CTA tile, 8 warps as 4x2 (64x64 warp tile), BK=32, 3-stage cp.async,
// single-sync pipeline, ldmatrix fragments.
// EPI: 0 = plain half out, 2 = fused assignment head (tanh + Wc2 dot + atomic)
#define STB_A (256 * 40 * 2)
#define STB_B (128 * 40 * 2)
#define HG_SMEM (3 * (STB_A + STB_B))
template <int K, int EPI>
__global__ void __launch_bounds__(256) hgemm(const __half* __restrict__ A,
                                             const __half* __restrict__ Bt,
                                             const float* __restrict__ bias,
                                             __half* __restrict__ C,
                                             const float* __restrict__ wc2) {
    constexpr int NT = K / 32;
    extern __shared__ __half hsh[];
    __half* As = hsh;                        // 3 x 256*40
    __half* Bs = hsh + 3 * 256 * 40;         // 3 x 128*40
    int tid = threadIdx.x;
    int wid = tid >> 5, lane = tid & 31;
    int g = lane >> 2, q = lane & 3;
    int wm = wid >> 1, wn = wid & 1;
    int m0 = blockIdx.y * 256, n0 = blockIdx.x * 128;

    int lr = tid >> 1, lc = tid & 1;   // row 0..127, half-row chunk
    const __half* Ag0 = A + (size_t)(m0 + lr) * K + lc * 16;
    const __half* Ag1 = A + (size_t)(m0 + lr + 128) * K + lc * 16;
    const __half* Bg = Bt + (size_t)(n0 + lr) * K + lc * 16;
    uint32_t sa0 = s2u(&As[lr * 40 + lc * 16]);
    uint32_t sa1 = s2u(&As[(lr + 128) * 40 + lc * 16]);
    uint32_t sb = s2u(&Bs[lr * 40 + lc * 16]);

    auto load_stage = [&](int kt, int st) {
        uint32_t oA = st * STB_A, oB = st * STB_B;
        cp16(sa0 + oA, Ag0 + kt * 32);
        cp16(sa0 + oA + 16, Ag0 + kt * 32 + 8);
        cp16(sa1 + oA, Ag1 + kt * 32);
        cp16(sa1 + oA + 16, Ag1 + kt * 32 + 8);
        cp16(sb + oB, Bg + kt * 32);
        cp16(sb + oB + 16, Bg + kt * 32 + 8);
        asm volatile("cp.async.commit_group;" ::: "memory");
    };

    uint32_t AsU = s2u(As), BsU = s2u(Bs);
    int laneA = (wm * 64 + (lane & 15)) * 40 + ((lane >> 4) & 1) * 8;
    int laneB = (wn * 64 + ((lane >> 4) & 1) * 8 + (lane & 7)) * 40
                + ((lane >> 3) & 1) * 8;

    float acc[4][8][4];
#pragma unroll
    for (int i = 0; i < 4; ++i)
#pragma unroll
        for (int j = 0; j < 8; ++j)
#pragma unroll
            for (int t = 0; t < 4; ++t) acc[i][j][t] = 0.f;

    load_stage(0, 0);
    if (NT > 1) load_stage(1, 1);

#pragma unroll 1
    for (int kt = 0; kt < NT; ++kt) {
        if (kt + 1 < NT) asm volatile("cp.async.wait_group 1;" ::: "memory");
        else             asm volatile("cp.async.wait_group 0;" ::: "memory");
        __syncthreads();
        if (kt + 2 < NT) load_stage(kt + 2, (kt + 2) % 3);

        uint32_t soA = (kt % 3) * STB_A, soB = (kt % 3) * STB_B;
#pragma unroll
        for (int ks = 0; ks < 2; ++ks) {
            uint32_t ko = ks * 32;   // bytes (16 halves)
            uint32_t af[4][4];
#pragma unroll
            for (int mi = 0; mi < 4; ++mi)
                ldm4(af[mi], AsU + soA + (laneA + mi * 16 * 40) * 2 + ko);
#pragma unroll
            for (int p = 0; p < 4; ++p) {
                uint32_t bf[4];
                ldm4(bf, BsU + soB + (laneB + p * 16 * 40) * 2 + ko);
#pragma unroll
                for (int mi = 0; mi < 4; ++mi) {
                    mma_f16(acc[mi][2 * p], af[mi], bf);
                    mma_f16(acc[mi][2 * p + 1], af[mi], bf + 2);
                }
            }
        }
    }

    if (EPI == 0) {
#pragma unroll
        for (int mi = 0; mi < 4; ++mi) {
            int row0 = m0 + wm * 64 + mi * 16 + g;
#pragma unroll
            for (int ni = 0; ni < 8; ++ni) {
                int col = n0 + wn * 64 + ni * 8 + 2 * q;
                *(half2*)(C + (size_t)row0 * HID + col) =
                    __floats2half2_rn(acc[mi][ni][0], acc[mi][ni][1]);
                *(half2*)(C + (size_t)(row0 + 8) * HID + col) =
                    __floats2half2_rn(acc[mi][ni][2], acc[mi][ni][3]);
            }
        }
    } else {
        // fused assignment head: s = sum_col tanh(acc+bc1[col]) * Wc2[col][:]
        float s[4][2][2];
#pragma unroll
        for (int mi = 0; mi < 4; ++mi)
#pragma unroll
            for (int r = 0; r < 2; ++r) { s[mi][r][0] = 0.f; s[mi][r][1] = 0.f; }
#pragma unroll
        for (int ni = 0; ni < 8; ++ni) {
            int col = n0 + wn * 64 + ni * 8 + 2 * q;
            float4 w4 = *(const float4*)(wc2 + col * 2);
            float2 bb = *(const float2*)(bias + col);
#pragma unroll
            for (int mi = 0; mi < 4; ++mi) {
                float v0 = tanhf(acc[mi][ni][0] + bb.x);
                float v1 = tanhf(acc[mi][ni][1] + bb.y);
                float v2 = tanhf(acc[mi][ni][2] + bb.x);
                float v3 = tanhf(acc[mi][ni][3] + bb.y);
                s[mi][0][0] += v0 * w4.x + v1 * w4.z;
                s[mi][0][1] += v0 * w4.y + v1 * w4.w;
                s[mi][1][0] += v2 * w4.x + v3 * w4.z;
                s[mi][1][1] += v2 * w4.y + v3 * w4.w;
            }
        }
#pragma unroll
        for (int mi = 0; mi < 4; ++mi)
#pragma unroll
            for (int r = 0; r < 2; ++r)
#pragma unroll
                for (int c = 0; c < 2; ++c) {
                    float v = s[mi][r][c];
                    v += __shfl_xor_sync(0xffffffff, v, 1);
                    v += __shfl_xor_sync(0xffffffff, v, 2);
                    s[mi][r][c] = v;
                }
        if (q == 0) {
#pragma unroll
            for (int mi = 0; mi < 4; ++mi)
#pragma unroll
                for (int r = 0; r < 2; ++r) {
                    int row = m0 + wm * 64 + mi * 16 + g + r * 8;
                    atomicAdd(&d_araw[row * 2], s[mi][r][0]);
                    atomicAdd(&d_araw[row * 2 + 1], s[mi][r][1]);
                }
        }
    }
}

// ---------------- tensor-core agg: H = A_g @ T_g + b ------------------------
// 256-col chunks: grid (NG, 2). Warps 2x4 (64 rows x 64 cols each).
// Ts stored [k:112][n:256] (row stride 264 halves -> 8-row bank-distinct).
#define TS2_LD 264
#define AGGH_SMEM ((128 * 120 + 112 * TS2_LD) * 2)
__global__ void __launch_bounds__(256) k_aggh(const __half* __restrict__ T,
                                              const float* __restrict__ bias,
                                              __half* __restrict__ Hh) {
    extern __shared__ __half aggsh[];
    __half* Ash = aggsh;                   // [128][120]
    __half* Ts = aggsh + 128 * 120;        // [112][264]
    int gph = blockIdx.x;
    int cb = blockIdx.y * 256;
    int tid = threadIdx.x;
    int wid = tid >> 5, lane = tid & 31;
    int g = lane >> 2, q = lane & 3;
    int wm = wid >> 2, wn = wid & 3;

    const uint4* Asrc = (const uint4*)(d_Ah + (size_t)gph * 128 * 120);
    uint4* Adst = (uint4*)Ash;
    for (int i = tid; i < 128 * 120 / 8; i += 256) Adst[i] = Asrc[i];

    // Ts[k][n]: 32 x uint4 (=256 halves) per row, zero pad k 100..111
    const __half* Tg = T + (size_t)gph * NPG * HID + cb;
    const uint4 z4 = make_uint4(0, 0, 0, 0);
    for (int i = tid; i < 112 * 32; i += 256) {
        int k = i >> 5, c = i & 31;
        uint4 v = (k < NPG) ? *(const uint4*)(Tg + (size_t)k * HID + c * 8) : z4;
        *(uint4*)(Ts + k * TS2_LD + c * 8) = v;
    }
    __syncthreads();

    uint32_t AshU = s2u(Ash), TsU = s2u(Ts);
    int laneA = (wm * 64 + (lane & 15)) * 120 + ((lane >> 4) & 1) * 8;
    int laneBt = (lane & 15) * TS2_LD + wn * 64 + ((lane >> 4) & 1) * 8;

    float acc[4][8][4];
#pragma unroll
    for (int i = 0; i < 4; ++i)
#pragma unroll
        for (int j = 0; j < 8; ++j)
#pragma unroll
            for (int t = 0; t < 4; ++t) acc[i][j][t] = 0.f;

#pragma unroll
    for (int k0 = 0; k0 < 112; k0 += 16) {
        uint32_t af[4][4];
#pragma unroll
        for (int mi = 0; mi < 4; ++mi)
            ldm4(af[mi], AshU + (laneA + mi * 16 * 120 + k0) * 2);
#pragma unroll
        for (int p = 0; p < 4; ++p) {
            uint32_t bf[4];
            ldm4t(bf, TsU + (laneBt + k0 * TS2_LD + p * 16) * 2);
#pragma unroll
            for (int mi = 0; mi < 4; ++mi) {
                mma_f16(acc[mi][2 * p], af[mi], bf);
                mma_f16(acc[mi][2 * p + 1], af[mi], bf + 2);
            }
        }
    }

#pragma unroll
    for (int mi = 0; mi < 4; ++mi) {
        int rl = wm * 64 + mi * 16 + g;
#pragma unroll
        for (int ni = 0; ni < 8; ++ni) {
            int col = cb + wn * 64 + ni * 8 + 2 * q;
            float2 bb = *(const float2*)(bias + col);
            if (rl < NPG) {
                size_t off = ((size_t)gph * NPG + rl) * HID + col;
                *(half2*)(Hh + off) =
                    __floats2half2_rn(acc[mi][ni][0] + bb.x, acc[mi][ni][1] + bb.y);
            }
            if (rl + 8 < NPG) {
                size_t off = ((size_t)gph * NPG + rl + 8) * HID + col;
                *(half2*)(Hh + off) =
                    __floats2half2_rn(acc[mi][ni][2] + bb.x, acc[mi][ni][3] + bb.y);
            }
        }
    }
}

// ---------------- fp32 tiled SGEMM (head only) ------------------------------
template <int EPI>
__global__ void sgemm(const float* __restrict__ A, const float* __restrict__ B,
                      const float* __restrict__ bias, float* __restrict__ C,
                      int M, int N, int K) {
    __shared__ float As[8][128];
    __shared__ float Bs[8][128];
    int tid = threadIdx.x;
    int m0 = blockIdx.y * 128;
    int n0 = blockIdx.x * 128;
    int arow = tid >> 1;
    int acol = (tid & 1) * 4;
    int brow = tid >> 5;
    int bcol = (tid & 31) * 4;
    int ty = tid >> 4;
    int tx = tid & 15;
    float acc[8][8] = {};

    for (int k0 = 0; k0 < K; k0 += 8) {
        float4 av = *(const float4*)(A + (size_t)(m0 + arow) * K + k0 + acol);
        As[acol + 0][arow] = av.x;
        As[acol + 1][arow] = av.y;
        As[acol + 2][arow] = av.z;
        As[acol + 3][arow] = av.w;
        *(float4*)(&Bs[brow][bcol]) =
            *(const float4*)(B + (size_t)(k0 + brow) * N + n0 + bcol);
        __syncthreads();
#pragma unroll
        for (int k = 0; k < 8; ++k) {
            float a[8], b[8];
            *(float4*)(a) = *(float4*)(&As[k][ty * 8]);
            *(float4*)(a + 4) = *(float4*)(&As[k][ty * 8 + 4]);
            *(float4*)(b) = *(float4*)(&Bs[k][tx * 8]);
            *(float4*)(b + 4) = *(float4*)(&Bs[k][tx * 8 + 4]);
#pragma unroll
            for (int i = 0; i < 8; ++i)
#pragma unroll
                for (int j = 0; j < 8; ++j) acc[i][j] = fmaf(a[i], b[j], acc[i][j]);
        }
        __syncthreads();
    }
#pragma unroll
    for (int i = 0; i < 8; ++i) {
        int row = m0 + ty * 8 + i;
#pragma unroll
        for (int j = 0; j < 8; j += 4) {
            int col = n0 + tx * 8 + j;
            float4 v = make_float4(acc[i][j], acc[i][j + 1], acc[i][j + 2], acc[i][j + 3]);
            if (EPI != 0) {
                float4 bb = *(const float4*)(bias + col);
                v.x += bb.x; v.y += bb.y; v.z += bb.z; v.w += bb.w;
                if (EPI == 1) {
                    v.x = tanhf(v.x); v.y = tanhf(v.y); v.z = tanhf(v.z); v.w = tanhf(v.w);
                } else {
                    v.x = fmaxf(v.x, 0.f); v.y = fmaxf(v.y, 0.f);
                    v.z = fmaxf(v.z, 0.f); v.w = fmaxf(v.w, 0.f);
                }
            }
            *(float4*)(C + (size_t)row * N + col) = v;
        }
    }
}

// ---------------- assignment softmax from raw logits ------------------------
__global__ void k_assign2(const float* __restrict__ bc2) {
    int n = blockIdx.x * blockDim.x + threadIdx.x;
    if (n < N_NODES) {
        float z0 = d_araw[2 * n] + bc2[0], z1 = d_araw[2 * n + 1] + bc2[1];
        float m = fmaxf(z0, z1);
        float e0 = expf(z0 - m), e1 = expf(z1 - m);
        float inv = 1.f / (e0 + e1);
        d_assign[2 * n] = e0 * inv;
        d_assign[2 * n + 1] = e1 * inv;
    }
}

// ---------------- pos + global h column sums (reads half h) -----------------
__global__ void k_pos(const __half* __restrict__ H) {
    __shared__ float a0[NPG];
    int g = blockIdx.x, c = threadIdx.x;
    if (c < NPG) a0[c] = d_assign[(g * NPG + c) * 2];
    __syncthreads();
    const __half* h = H + (size_t)g * NPG * HID;
    float acc = 0.f, gs = 0.f;
    for (int n = 0; n < NPG; ++n) {
        float hv = __half2float(h[n * HID + c]);
        acc = fmaf(a0[n], hv, acc);
        gs += hv;
    }
    d_pos[g * HID + c] = acc;
    atomicAdd(&d_gvec[c], gs);
}

// ---------------- new_adj + penalty (fused, per-graph atomic) ---------------
__global__ void k_newadj(const int* __restrict__ ei) {
    __shared__ float sa[NPG * 2];
    __shared__ float red[4][4];
    int g = blockIdx.x, tid = threadIdx.x;
    if (tid < NPG * 2) sa[tid] = d_assign[g * NPG * 2 + tid];
    __syncthreads();
    float a00 = 0, a01 = 0, a10 = 0, a11 = 0;
    for (int e = tid; e < EPG; e += 128) {
        int s = ei[g * EPG + e] - g * NPG;
        int d = ei[N_EDGES + g * EPG + e] - g * NPG;
        float s0 = sa[2 * s], s1 = sa[2 * s + 1];
        float t0 = sa[2 * d], t1 = sa[2 * d + 1];
        a00 = fmaf(s0, t0, a00); a01 = fmaf(s0, t1, a01);
        a10 = fmaf(s1, t0, a10); a11 = fmaf(s1, t1, a11);
    }
#pragma unroll
    for (int o = 16; o > 0; o >>= 1) {
        a00 += __shfl_xor_sync(0xffffffff, a00, o);
        a01 += __shfl_xor_sync(0xffffffff, a01, o);
        a10 += __shfl_xor_sync(0xffffffff, a10, o);
        a11 += __shfl_xor_sync(0xffffffff, a11, o);
    }
    int warp = tid >> 5, lane = tid & 31;
    if (lane == 0) {
        red[warp][0] = a00; red[warp][1] = a01;
        red[warp][2] = a10; red[warp][3] = a11;
    }
    __syncthreads();
    if (tid == 0) {
        float v00 = red[0][0] + red[1][0] + red[2][0] + red[3][0];
        float v01 = red[0][1] + red[1][1] + red[2][1] + red[3][1];
        float v10 = red[0][2] + red[1][2] + red[2][2] + red[3][2];
        float v11 = red[0][3] + red[1][3] + red[2][3] + red[3][3];
        float r0 = fmaxf(fabsf(v00) + fabsf(v01), EPSV);
        float r1 = fmaxf(fabsf(v10) + fabsf(v11), EPSV);
        float dd0 = v00 / r0 - 1.f, dd1 = v11 / r1 - 1.f;
        atomicAdd(&d_scal[2], dd0 * dd0 + dd1 * dd1);
    }
}

// ---------------- norm reductions ------------------------------------------
__global__ void k_sumsq_pos() {
    __shared__ float red[256];
    int tid = threadIdx.x;
    float s = 0.f;
    for (int i = blockIdx.x * 256 + tid; i < NG * HID; i += gridDim.x * 256) {
        float v = d_pos[i];
        s = fmaf(v, v, s);
    }
    red[tid] = s;
    __syncthreads();
    for (int o = 128; o > 0; o >>= 1) {
        if (tid < o) red[tid] += red[tid + o];
        __syncthreads();
    }
    if (tid == 0) atomicAdd(&d_scal[0], red[0]);
}

__global__ void k_pg() {
    __shared__ float red[HID];
    int t = threadIdx.x;
    float v = d_gvec[t] * (1.f / (float)N_NODES);
    red[t] = v * v;
    __syncthreads();
    for (int s = 256; s > 0; s >>= 1) {
        if (t < s) red[t] += red[t + s];
        __syncthreads();
    }
    if (t == 0) d_scal[1] = red[0] * (1.f / (float)HID);
}

// ---------------- final outputs: pos, gemb, penalty -------------------------
__global__ void k_final(float* __restrict__ out) {
    int i = blockIdx.x * blockDim.x + threadIdx.x;
    if (i == 0) out[OUT_PEN] = d_scal[2] * (1.f / (NG * 2.f));
    if (i < NG * HID) {
        float ms = d_scal[0] * (1.f / (float)(NG * HID));
        float sc = (ms > 1.f) ? rsqrtf(ms) : 1.f;
        float v = d_pos[i] * sc;
        d_pos[i] = v;
        out[OUT_POS + i] = v;
        float ms2 = d_scal[1];
        float sc2 = (ms2 > 1.f) ? rsqrtf(ms2) : 1.f;
        out[OUT_GEMB + i] = d_gvec[i & (HID - 1)] * (1.f / (float)N_NODES) * sc2;
    }
}

// ---------------- head ------------------------------------------------------
__global__ void k_head(const float* __restrict__ Z, const float* __restrict__ Wl2,
                       const float* __restrict__ bl2, float* __restrict__ out) {
    __shared__ float w[HID * 6];
    int tid = threadIdx.x;
    for (int i = tid; i < HID * 6; i += 128) w[i] = Wl2[i];
    __syncthreads();
    int warp = tid >> 5, lane = tid & 31;
    int row = blockIdx.x * 4 + warp;
    const float* z = Z + (size_t)row * HID;
    float s[6] = {0, 0, 0, 0, 0, 0};
    for (int k = lane; k < HID; k += 32) {
        float zv = z[k];
#pragma unroll
        for (int j = 0; j < 6; ++j) s[j] = fmaf(zv, w[k * 6 + j], s[j]);
    }
#pragma unroll
    for (int o = 16; o > 0; o >>= 1)
#pragma unroll
        for (int j = 0; j < 6; ++j) s[j] += __shfl_xor_sync(0xffffffff, s[j], o);
    if (lane == 0) {
        float o6[6], m = -1e30f;
#pragma unroll
        for (int j = 0; j < 6; ++j) { o6[j] = s[j] + bl2[j]; m = fmaxf(m, o6[j]); }
        float sum = 0.f;
#pragma unroll
        for (int j = 0; j < 6; ++j) sum += expf(o6[j] - m);
        float lse = m + logf(sum);
#pragma unroll
        for (int j = 0; j < 6; ++j) out[OUT_LOGP + row * 6 + j] = o6[j] - lse;
    }
}

// ---------------- launch ----------------------------------------------------
extern "C" void kernel_launch(void* const* d_in, const int* in_sizes, int n_in,
                              void* d_out, int out_size) {
    const float* x   = (const float*)d_in[0];
    const int*   ei  = (const int*)d_in[1];
    const float* W1  = (const float*)d_in[4];
    const float* b1  = (const float*)d_in[5];
    const float* W2  = (const float*)d_in[6];
    const float* b2  = (const float*)d_in[7];
    const float* W3  = (const float*)d_in[8];
    const float* b3  = (const float*)d_in[9];
    const float* Wc1 = (const float*)d_in[10];
    const float* bc1 = (const float*)d_in[11];
    const float* Wc2 = (const float*)d_in[12];
    const float* bc2 = (const float*)d_in[13];
    const float* Wl1 = (const float*)d_in[14];
    const float* bl1 = (const float*)d_in[15];
    const float* Wl2 = (const float*)d_in[16];
    const float* bl2 = (const float*)d_in[17];
    float* out = (float*)d_out;

    float *pT, *pPos;
    __half *pTh, *pHh, *pXh;
    cudaGetSymbolAddress((void**)&pT, d_T);
    cudaGetSymbolAddress((void**)&pPos, d_pos);
    cudaGetSymbolAddress((void**)&pTh, d_Th);
    cudaGetSymbolAddress((void**)&pHh, d_Hh);
    cudaGetSymbolAddress((void**)&pXh, d_Xh);

    cudaFuncSetAttribute(k_aggh, cudaFuncAttributeMaxDynamicSharedMemorySize, AGGH_SMEM);
    cudaFuncSetAttribute(hgemm<FIN, 0>, cudaFuncAttributeMaxDynamicSharedMemorySize, HG_SMEM);
    cudaFuncSetAttribute(hgemm<HID, 0>, cudaFuncAttributeMaxDynamicSharedMemorySize, HG_SMEM);
    cudaFuncSetAttribute(hgemm<HID, 2>, cudaFuncAttributeMaxDynamicSharedMemorySize, HG_SMEM);

    __half* pWh;
    cudaGetSymbolAddress((void**)&pWh, d_Wh);
    __half* Wh0 = pWh;
    __half* Wh1 = pWh + HID * HID;
    __half* Wh2 = pWh + 2 * HID * HID;
    __half* Wh3 = pWh + 3 * HID * HID;

    // fused graph structure build + misc zero + weight prep
    k_zero_misc<<<100, 1024>>>();
    k_build<<<NG, 256>>>(ei);
    k_transpose_all<<<dim3(HID / 32, HID / 32, 4), dim3(32, 8)>>>(W1, W2, W3, Wc1);
    k_x2h<<<(N_NODES * FIN / 2 + 255) / 256, 256>>>((const float2*)x, (__half2*)pXh);

    dim3 gBig(HID / 128, N_NODES / 256);
    dim3 gAgg(NG, 2);

    // 3 GCN layers: T = H@W (fp16 tensor) ; H = A_hat @ T + b (fp16 tensor)
    hgemm<FIN, 0><<<gBig, 256, HG_SMEM>>>(pXh, Wh0, nullptr, pTh, nullptr);
    k_aggh<<<gAgg, 256, AGGH_SMEM>>>(pTh, b1, pHh);
    hgemm<HID, 0><<<gBig, 256, HG_SMEM>>>(pHh, Wh1, nullptr, pTh, nullptr);
    k_aggh<<<gAgg, 256, AGGH_SMEM>>>(pTh, b2, pHh);
    hgemm<HID, 0><<<gBig, 256, HG_SMEM>>>(pHh, Wh2, nullptr, pTh, nullptr);
    k_aggh<<<gAgg, 256, AGGH_SMEM>>>(pTh, b3, pHh);

    // assignment fused into 4th GEMM epilogue, then softmax
    hgemm<HID, 2><<<gBig, 256, HG_SMEM>>>(pHh, Wh3, bc1, pTh, Wc2);
    k_assign2<<<(N_NODES + 255) / 256, 256>>>(bc2);

    // pooling / penalty
    k_pos<<<NG, HID>>>(pHh);
    k_newadj<<<NG, 128>>>(ei);

    // normalizations + final outputs
    k_sumsq_pos<<<256, 256>>>();
    k_pg<<<1, HID>>>();
    k_final<<<1024, 256>>>(out);

    // head MLP on normalized pos (fp32)
    dim3 gHead(HID / 128, NG / 128);
    sgemm<2><<<gHead, 256>>>(pPos, Wl1, bl1, pT, NG, HID, HID);
    k_head<<<NG / 4, 128>>>(pT, Wl2, bl2, out);
}

// round 12
// speedup vs baseline: 1.0921x; 1.0921x over previous
#include <cuda_runtime.h>
#include <cuda_fp16.h>
#include <math.h>
#include <cstdint>

#define N_NODES 51200
#define N_EDGES 819200
#define NG 512
#define NPG 100
#define EPG 1600
#define HID 512
#define FIN 128
#define EPSV 1e-5f

#define OUT_LOGP 0
#define OUT_POS 3072
#define OUT_GEMB 265216
#define OUT_PEN 527360

// ---------------- scratch (static device allocations; no cudaMalloc) --------
__device__ __half d_Ah[NG * 128 * 120];        // padded half adjacency [g][m:128][k:120]
__device__ __half d_Th[N_NODES * HID];         // GEMM output (half)
__device__ __half d_Hh[N_NODES * HID];         // agg output (half)
__device__ __half d_Xh[N_NODES * FIN];         // x in half
__device__ __half d_Wh[4][HID * HID];          // transposed half weights [N][K]
__device__ float d_T[N_NODES * HID];           // fp32 scratch (head path)
__device__ float d_araw[N_NODES * 2];          // raw assignment logits (atomic acc)
__device__ float d_assign[N_NODES * 2];
__device__ float d_pos[NG * HID];
__device__ float d_gvec[HID];
__device__ float d_scal[4];                    // [0]=pos ss, [1]=pg ms, [2]=penalty acc

// ---------------- ptx helpers ----------------------------------------------
__device__ __forceinline__ uint32_t s2u(const void* p) {
    uint32_t a;
    asm("{ .reg .u64 t; cvta.to.shared.u64 t, %1; cvt.u32.u64 %0, t; }"
        : "=r"(a) : "l"(p));
    return a;
}
__device__ __forceinline__ void cp16(uint32_t s, const void* g) {
    asm volatile("cp.async.cg.shared.global [%0], [%1], 16;" :: "r"(s), "l"(g));
}
__device__ __forceinline__ void mma_f16(float* c, const uint32_t* a, const uint32_t* b) {
    asm volatile(
        "mma.sync.aligned.m16n8k16.row.col.f32.f16.f16.f32 "
        "{%0,%1,%2,%3}, {%4,%5,%6,%7}, {%8,%9}, {%0,%1,%2,%3};"
        : "+f"(c[0]), "+f"(c[1]), "+f"(c[2]), "+f"(c[3])
        : "r"(a[0]), "r"(a[1]), "r"(a[2]), "r"(a[3]), "r"(b[0]), "r"(b[1]));
}
__device__ __forceinline__ void ldm4(uint32_t* r, uint32_t addr) {
    asm volatile("ldmatrix.sync.aligned.m8n8.x4.shared.b16 {%0,%1,%2,%3}, [%4];"
                 : "=r"(r[0]), "=r"(r[1]), "=r"(r[2]), "=r"(r[3]) : "r"(addr));
}
__device__ __forceinline__ void ldm4t(uint32_t* r, uint32_t addr) {
    asm volatile("ldmatrix.sync.aligned.m8n8.x4.trans.shared.b16 {%0,%1,%2,%3}, [%4];"
                 : "=r"(r[0]), "=r"(r[1]), "=r"(r[2]), "=r"(r[3]) : "r"(addr));
}

// ---------------- fused per-graph structure build ---------------------------
__global__ void __launch_bounds__(256) k_build(const int* __restrict__ ei) {
    __shared__ float Adj[NPG * NPG];
    __shared__ float deg[NPG];
    __shared__ float dis[NPG];
    int g = blockIdx.x, tid = threadIdx.x;
    for (int i = tid; i < NPG * NPG; i += 256) Adj[i] = 0.f;
    if (tid < NPG) deg[tid] = 0.f;
    __syncthreads();
    const int* src = ei + g * EPG;
    const int* dst = ei + N_EDGES + g * EPG;
    int base = g * NPG;
    for (int e = tid; e < EPG; e += 256) atomicAdd(&deg[dst[e] - base], 1.f);
    __syncthreads();
    if (tid < NPG) dis[tid] = rsqrtf(deg[tid] + 1.f);
    __syncthreads();
    for (int e = tid; e < EPG; e += 256) {
        int s = src[e] - base, d = dst[e] - base;
        atomicAdd(&Adj[d * NPG + s], dis[s] * dis[d]);
    }
    __syncthreads();
    if (tid < NPG) Adj[tid * NPG + tid] += dis[tid] * dis[tid];
    __syncthreads();
    __half2* out = (__half2*)(d_Ah + (size_t)g * 128 * 120);
    for (int i = tid; i < 128 * 60; i += 256) {
        int r = i / 60, k = (i % 60) * 2;
        float v0 = (r < NPG && k < NPG) ? Adj[r * NPG + k] : 0.f;
        float v1 = (r < NPG && k + 1 < NPG) ? Adj[r * NPG + k + 1] : 0.f;
        out[i] = __floats2half2_rn(v0, v1);
    }
}

__global__ void k_zero_misc() {   // grid 100 x 1024
    int i = blockIdx.x * 1024 + threadIdx.x;
    if (i < N_NODES * 2) d_araw[i] = 0.f;
    if (i < HID) d_gvec[i] = 0.f;
    if (i < 4) d_scal[i] = 0.f;
}

// ---------------- all 4 weight transposes in one launch ---------------------
__global__ void k_transpose_all(const float* __restrict__ W1,
                                const float* __restrict__ W2,
                                const float* __restrict__ W3,
                                const float* __restrict__ Wc1) {
    __shared__ float tile[32][33];
    int z = blockIdx.z;
    const float* W = (z == 0) ? W1 : (z == 1) ? W2 : (z == 2) ? W3 : Wc1;
    int K = (z == 0) ? FIN : HID;
    int k0 = blockIdx.y * 32, n0 = blockIdx.x * 32;
    if (k0 >= K) return;
    __half* Wt = d_Wh[z];
    int tx = threadIdx.x, ty = threadIdx.y;
    for (int j = ty; j < 32; j += 8) tile[j][tx] = W[(size_t)(k0 + j) * HID + n0 + tx];
    __syncthreads();
    for (int j = ty; j < 32; j += 8)
        Wt[(size_t)(n0 + j) * K + k0 + tx] = __float2half_rn(tile[tx][j]);
}

__global__ void k_x2h(const float2* __restrict__ x, __half2* __restrict__ o) {
    int i = blockIdx.x * blockDim.x + threadIdx.x;
    if (i < N_NODES * FIN / 2) o[i] = __float22half2_rn(x[i]);
}

// ---------------- fp16 mma GEMM: C[M,512] = A[M,K] @ Wt[512,K]^T ------------
// 256x128 CTA tile, 8 warps as 4x2 (64x64 warp tile), BK=32, 3-stage cp.async,
// single-sync pipeline, ldmatrix fragments.
// EPI: 0 = plain half out, 2 = fused assignment head (tanh + Wc2 dot + atomic)
#define STB_A (256 * 40 * 2)
#define STB_B (128 * 40 * 2)
#define HG_SMEM (3 * (STB_A + STB_B))
template <int K, int EPI>
__global__ void __launch_bounds__(256) hgemm(const __half* __restrict__ A,
                                             const __half* __restrict__ Bt,
                                             const float* __restrict__ bias,
                                             __half* __restrict__ C,
                                             const float* __restrict__ wc2) {
    constexpr int NT = K / 32;
    extern __shared__ __half hsh[];
    __half* As = hsh;                        // 3 x 256*40
    __half* Bs = hsh + 3 * 256 * 40;         // 3 x 128*40
    int tid = threadIdx.x;
    int wid = tid >> 5, lane = tid & 31;
    int g = lane >> 2, q = lane & 3;
    int wm = wid >> 1, wn = wid & 1;
    int m0 = blockIdx.y * 256, n0 = blockIdx.x * 128;

    int lr = tid >> 1, lc = tid & 1;   // row 0..127, half-row chunk
    const __half* Ag0 = A + (size_t)(m0 + lr) * K + lc * 16;
    const __half* Ag1 = A + (size_t)(m0 + lr + 128) * K + lc * 16;
    const __half* Bg = Bt + (size_t)(n0 + lr) * K + lc * 16;
    uint32_t sa0 = s2u(&As[lr * 40 + lc * 16]);
    uint32_t sa1 = s2u(&As[(lr + 128) * 40 + lc * 16]);
    uint32_t sb = s2u(&Bs[lr * 40 + lc * 16]);

    auto load_stage = [&](int kt, int st) {
        uint32_t oA = st * STB_A, oB = st * STB_B;
        cp16(sa0 + oA, Ag0 + kt * 32);
        cp16(sa0 + oA + 16, Ag0 + kt * 32 + 8);
        cp16(sa1 + oA, Ag1 + kt * 32);
        cp16(sa1 + oA + 16, Ag1 + kt * 32 + 8);
        cp16(sb + oB, Bg + kt * 32);
        cp16(sb + oB + 16, Bg + kt * 32 + 8);
        asm volatile("cp.async.commit_group;" ::: "memory");
    };

    uint32_t AsU = s2u(As), BsU = s2u(Bs);
    int laneA = (wm * 64 + (lane & 15)) * 40 + ((lane >> 4) & 1) * 8;
    int laneB = (wn * 64 + ((lane >> 4) & 1) * 8 + (lane & 7)) * 40
                + ((lane >> 3) & 1) * 8;

    float acc[4][8][4];
#pragma unroll
    for (int i = 0; i < 4; ++i)
#pragma unroll
        for (int j = 0; j < 8; ++j)
#pragma unroll
            for (int t = 0; t < 4; ++t) acc[i][j][t] = 0.f;

    load_stage(0, 0);
    if (NT > 1) load_stage(1, 1);

#pragma unroll 1
    for (int kt = 0; kt < NT; ++kt) {
        if (kt + 1 < NT) asm volatile("cp.async.wait_group 1;" ::: "memory");
        else             asm volatile("cp.async.wait_group 0;" ::: "memory");
        __syncthreads();
        if (kt + 2 < NT) load_stage(kt + 2, (kt + 2) % 3);

        uint32_t soA = (kt % 3) * STB_A, soB = (kt % 3) * STB_B;
#pragma unroll
        for (int ks = 0; ks < 2; ++ks) {
            uint32_t ko = ks * 32;   // bytes (16 halves)
            uint32_t af[4][4];
#pragma unroll
            for (int mi = 0; mi < 4; ++mi)
                ldm4(af[mi], AsU + soA + (laneA + mi * 16 * 40) * 2 + ko);
#pragma unroll
            for (int p = 0; p < 4; ++p) {
                uint32_t bf[4];
                ldm4(bf, BsU + soB + (laneB + p * 16 * 40) * 2 + ko);
#pragma unroll
                for (int mi = 0; mi < 4; ++mi) {
                    mma_f16(acc[mi][2 * p], af[mi], bf);
                    mma_f16(acc[mi][2 * p + 1], af[mi], bf + 2);
                }
            }
        }
    }

    if (EPI == 0) {
#pragma unroll
        for (int mi = 0; mi < 4; ++mi) {
            int row0 = m0 + wm * 64 + mi * 16 + g;
#pragma unroll
            for (int ni = 0; ni < 8; ++ni) {
                int col = n0 + wn * 64 + ni * 8 + 2 * q;
                *(half2*)(C + (size_t)row0 * HID + col) =
                    __floats2half2_rn(acc[mi][ni][0], acc[mi][ni][1]);
                *(half2*)(C + (size_t)(row0 + 8) * HID + col) =
                    __floats2half2_rn(acc[mi][ni][2], acc[mi][ni][3]);
            }
        }
    } else {
        // fused assignment head: s = sum_col tanh(acc+bc1[col]) * Wc2[col][:]
        float s[4][2][2];
#pragma unroll
        for (int mi = 0; mi < 4; ++mi)
#pragma unroll
            for (int r = 0; r < 2; ++r) { s[mi][r][0] = 0.f; s[mi][r][1] = 0.f; }
#pragma unroll
        for (int ni = 0; ni < 8; ++ni) {
            int col = n0 + wn * 64 + ni * 8 + 2 * q;
            float4 w4 = *(const float4*)(wc2 + col * 2);
            float2 bb = *(const float2*)(bias + col);
#pragma unroll
            for (int mi = 0; mi < 4; ++mi) {
                float v0 = tanhf(acc[mi][ni][0] + bb.x);
                float v1 = tanhf(acc[mi][ni][1] + bb.y);
                float v2 = tanhf(acc[mi][ni][2] + bb.x);
                float v3 = tanhf(acc[mi][ni][3] + bb.y);
                s[mi][0][0] += v0 * w4.x + v1 * w4.z;
                s[mi][0][1] += v0 * w4.y + v1 * w4.w;
                s[mi][1][0] += v2 * w4.x + v3 * w4.z;
                s[mi][1][1] += v2 * w4.y + v3 * w4.w;
            }
        }
#pragma unroll
        for (int mi = 0; mi < 4; ++mi)
#pragma unroll
            for (int r = 0; r < 2; ++r)
#pragma unroll
                for (int c = 0; c < 2; ++c) {
                    float v = s[mi][r][c];
                    v += __shfl_xor_sync(0xffffffff, v, 1);
                    v += __shfl_xor_sync(0xffffffff, v, 2);
                    s[mi][r][c] = v;
                }
        if (q == 0) {
#pragma unroll
            for (int mi = 0; mi < 4; ++mi)
#pragma unroll
                for (int r = 0; r < 2; ++r) {
                    int row = m0 + wm * 64 + mi * 16 + g + r * 8;
                    atomicAdd(&d_araw[row * 2], s[mi][r][0]);
                    atomicAdd(&d_araw[row * 2 + 1], s[mi][r][1]);
                }
        }
    }
}

// ---------------- tensor-core agg: H = A_g @ T_g + b ------------------------
// Ts stored [k:112][n:128] (row stride 136 halves), B frags via ldmatrix.trans.
// Grid (NG, 4), warps 2x2 (32 rows x 64 cols each). R9-proven configuration.
#define TS_LD 136
#define AGGH_SMEM ((128 * 120 + 112 * TS_LD) * 2)
__global__ void __launch_bounds__(256) k_aggh(const __half* __restrict__ T,
                                              const float* __restrict__ bias,
                                              __half* __restrict__ Hh) {
    extern __shared__ __half aggsh[];
    __half* Ash = aggsh;                   // [128][120]
    __half* Ts = aggsh + 128 * 120;        // [112][136]
    int gph = blockIdx.x;
    int cb = blockIdx.y * 128;
    int tid = threadIdx.x;
    int wid = tid >> 5, lane = tid & 31;
    int g = lane >> 2, q = lane & 3;
    int wm = wid >> 1, wn = wid & 1;

    const uint4* Asrc = (const uint4*)(d_Ah + (size_t)gph * 128 * 120);
    uint4* Adst = (uint4*)Ash;
    for (int i = tid; i < 128 * 120 / 8; i += 256) Adst[i] = Asrc[i];

    // Ts[k][n] direct copy: 16 x uint4 (=128 halves) per row, zero pad k 100..111
    const __half* Tg = T + (size_t)gph * NPG * HID + cb;
    const uint4 z4 = make_uint4(0, 0, 0, 0);
    for (int i = tid; i < 112 * 16; i += 256) {
        int k = i >> 4, c = i & 15;
        uint4 v = (k < NPG) ? *(const uint4*)(Tg + (size_t)k * HID + c * 8) : z4;
        *(uint4*)(Ts + k * TS_LD + c * 8) = v;
    }
    __syncthreads();

    uint32_t AshU = s2u(Ash), TsU = s2u(Ts);
    int laneA = (wm * 32 + (lane & 15)) * 120 + ((lane >> 4) & 1) * 8;
    int laneBt = (lane & 15) * TS_LD + wn * 64 + ((lane >> 4) & 1) * 8;

    float acc[2][8][4];
#pragma unroll
    for (int i = 0; i < 2; ++i)
#pragma unroll
        for (int j = 0; j < 8; ++j)
#pragma unroll
            for (int t = 0; t < 4; ++t) acc[i][j][t] = 0.f;

#pragma unroll
    for (int k0 = 0; k0 < 112; k0 += 16) {
        uint32_t af[2][4];
#pragma unroll
        for (int mi = 0; mi < 2; ++mi)
            ldm4(af[mi], AshU + (laneA + mi * 16 * 120 + k0) * 2);
#pragma unroll
        for (int p = 0; p < 4; ++p) {
            uint32_t bf[4];
            ldm4t(bf, TsU + (laneBt + k0 * TS_LD + p * 16) * 2);
#pragma unroll
            for (int mi = 0; mi < 2; ++mi) {
                mma_f16(acc[mi][2 * p], af[mi], bf);
                mma_f16(acc[mi][2 * p + 1], af[mi], bf + 2);
            }
        }
    }

#pragma unroll
    for (int mi = 0; mi < 2; ++mi) {
        int rl = wm * 32 + mi * 16 + g;
#pragma unroll
        for (int ni = 0; ni < 8; ++ni) {
            int col = cb + wn * 64 + ni * 8 + 2 * q;
            float2 bb = *(const float2*)(bias + col);
            if (rl < NPG) {
                size_t off = ((size_t)gph * NPG + rl) * HID + col;
                *(half2*)(Hh + off) =
                    __floats2half2_rn(acc[mi][ni][0] + bb.x, acc[mi][ni][1] + bb.y);
            }
            if (rl + 8 < NPG) {
                size_t off = ((size_t)gph * NPG + rl + 8) * HID + col;
                *(half2*)(Hh + off) =
                    __floats2half2_rn(acc[mi][ni][2] + bb.x, acc[mi][ni][3] + bb.y);
            }
        }
    }
}

// ---------------- fp32 tiled SGEMM (head only) ------------------------------
template <int EPI>
__global__ void sgemm(const float* __restrict__ A, const float* __restrict__ B,
                      const float* __restrict__ bias, float* __restrict__ C,
                      int M, int N, int K) {
    __shared__ float As[8][128];
    __shared__ float Bs[8][128];
    int tid = threadIdx.x;
    int m0 = blockIdx.y * 128;
    int n0 = blockIdx.x * 128;
    int arow = tid >> 1;
    int acol = (tid & 1) * 4;
    int brow = tid >> 5;
    int bcol = (tid & 31) * 4;
    int ty = tid >> 4;
    int tx = tid & 15;
    float acc[8][8] = {};

    for (int k0 = 0; k0 < K; k0 += 8) {
        float4 av = *(const float4*)(A + (size_t)(m0 + arow) * K + k0 + acol);
        As[acol + 0][arow] = av.x;
        As[acol + 1][arow] = av.y;
        As[acol + 2][arow] = av.z;
        As[acol + 3][arow] = av.w;
        *(float4*)(&Bs[brow][bcol]) =
            *(const float4*)(B + (size_t)(k0 + brow) * N + n0 + bcol);
        __syncthreads();
#pragma unroll
        for (int k = 0; k < 8; ++k) {
            float a[8], b[8];
            *(float4*)(a) = *(float4*)(&As[k][ty * 8]);
            *(float4*)(a + 4) = *(float4*)(&As[k][ty * 8 + 4]);
            *(float4*)(b) = *(float4*)(&Bs[k][tx * 8]);
            *(float4*)(b + 4) = *(float4*)(&Bs[k][tx * 8 + 4]);
#pragma unroll
            for (int i = 0; i < 8; ++i)
#pragma unroll
                for (int j = 0; j < 8; ++j) acc[i][j] = fmaf(a[i], b[j], acc[i][j]);
        }
        __syncthreads();
    }
#pragma unroll
    for (int i = 0; i < 8; ++i) {
        int row = m0 + ty * 8 + i;
#pragma unroll
        for (int j = 0; j < 8; j += 4) {
            int col = n0 + tx * 8 + j;
            float4 v = make_float4(acc[i][j], acc[i][j + 1], acc[i][j + 2], acc[i][j + 3]);
            if (EPI != 0) {
                float4 bb = *(const float4*)(bias + col);
                v.x += bb.x; v.y += bb.y; v.z += bb.z; v.w += bb.w;
                if (EPI == 1) {
                    v.x = tanhf(v.x); v.y = tanhf(v.y); v.z = tanhf(v.z); v.w = tanhf(v.w);
                } else {
                    v.x = fmaxf(v.x, 0.f); v.y = fmaxf(v.y, 0.f);
                    v.z = fmaxf(v.z, 0.f); v.w = fmaxf(v.w, 0.f);
                }
            }
            *(float4*)(C + (size_t)row * N + col) = v;
        }
    }
}

// ---------------- assignment softmax from raw logits ------------------------
__global__ void k_assign2(const float* __restrict__ bc2) {
    int n = blockIdx.x * blockDim.x + threadIdx.x;
    if (n < N_NODES) {
        float z0 = d_araw[2 * n] + bc2[0], z1 = d_araw[2 * n + 1] + bc2[1];
        float m = fmaxf(z0, z1);
        float e0 = expf(z0 - m), e1 = expf(z1 - m);
        float inv = 1.f / (e0 + e1);
        d_assign[2 * n] = e0 * inv;
        d_assign[2 * n + 1] = e1 * inv;
    }
}

// ---------------- pos + global h column sums (reads half h) -----------------
__global__ void k_pos(const __half* __restrict__ H) {
    __shared__ float a0[NPG];
    int g = blockIdx.x, c = threadIdx.x;
    if (c < NPG) a0[c] = d_assign[(g * NPG + c) * 2];
    __syncthreads();
    const __half* h = H + (size_t)g * NPG * HID;
    float acc = 0.f, gs = 0.f;
    for (int n = 0; n < NPG; ++n) {
        float hv = __half2float(h[n * HID + c]);
        acc = fmaf(a0[n], hv, acc);
        gs += hv;
    }
    d_pos[g * HID + c] = acc;
    atomicAdd(&d_gvec[c], gs);
}

// ---------------- new_adj + penalty (fused, per-graph atomic) ---------------
__global__ void k_newadj(const int* __restrict__ ei) {
    __shared__ float sa[NPG * 2];
    __shared__ float red[4][4];
    int g = blockIdx.x, tid = threadIdx.x;
    if (tid < NPG * 2) sa[tid] = d_assign[g * NPG * 2 + tid];
    __syncthreads();
    float a00 = 0, a01 = 0, a10 = 0, a11 = 0;
    for (int e = tid; e < EPG; e += 128) {
        int s = ei[g * EPG + e] - g * NPG;
        int d = ei[N_EDGES + g * EPG + e] - g * NPG;
        float s0 = sa[2 * s], s1 = sa[2 * s + 1];
        float t0 = sa[2 * d], t1 = sa[2 * d + 1];
        a00 = fmaf(s0, t0, a00); a01 = fmaf(s0, t1, a01);
        a10 = fmaf(s1, t0, a10); a11 = fmaf(s1, t1, a11);
    }
#pragma unroll
    for (int o = 16; o > 0; o >>= 1) {
        a00 += __shfl_xor_sync(0xffffffff, a00, o);
        a01 += __shfl_xor_sync(0xffffffff, a01, o);
        a10 += __shfl_xor_sync(0xffffffff, a10, o);
        a11 += __shfl_xor_sync(0xffffffff, a11, o);
    }
    int warp = tid >> 5, lane = tid & 31;
    if (lane == 0) {
        red[warp][0] = a00; red[warp][1] = a01;
        red[warp][2] = a10; red[warp][3] = a11;
    }
    __syncthreads();
    if (tid == 0) {
        float v00 = red[0][0] + red[1][0] + red[2][0] + red[3][0];
        float v01 = red[0][1] + red[1][1] + red[2][1] + red[3][1];
        float v10 = red[0][2] + red[1][2] + red[2][2] + red[3][2];
        float v11 = red[0][3] + red[1][3] + red[2][3] + red[3][3];
        float r0 = fmaxf(fabsf(v00) + fabsf(v01), EPSV);
        float r1 = fmaxf(fabsf(v10) + fabsf(v11), EPSV);
        float dd0 = v00 / r0 - 1.f, dd1 = v11 / r1 - 1.f;
        atomicAdd(&d_scal[2], dd0 * dd0 + dd1 * dd1);
    }
}

// ---------------- norm reductions ------------------------------------------
__global__ void k_sumsq_pos() {
    __shared__ float red[256];
    int tid = threadIdx.x;
    float s = 0.f;
    for (int i = blockIdx.x * 256 + tid; i < NG * HID; i += gridDim.x * 256) {
        float v = d_pos[i];
        s = fmaf(v, v, s);
    }
    red[tid] = s;
    __syncthreads();
    for (int o = 128; o > 0; o >>= 1) {
        if (tid < o) red[tid] += red[tid + o];
        __syncthreads();
    }
    if (tid == 0) atomicAdd(&d_scal[0], red[0]);
}

__global__ void k_pg() {
    __shared__ float red[HID];
    int t = threadIdx.x;
    float v = d_gvec[t] * (1.f / (float)N_NODES);
    red[t] = v * v;
    __syncthreads();
    for (int s = 256; s > 0; s >>= 1) {
        if (t < s) red[t] += red[t + s];
        __syncthreads();
    }
    if (t == 0) d_scal[1] = red[0] * (1.f / (float)HID);
}

// ---------------- final outputs: pos, gemb, penalty -------------------------
__global__ void k_final(float* __restrict__ out) {
    int i = blockIdx.x * blockDim.x + threadIdx.x;
    if (i == 0) out[OUT_PEN] = d_scal[2] * (1.f / (NG * 2.f));
    if (i < NG * HID) {
        float ms = d_scal[0] * (1.f / (float)(NG * HID));
        float sc = (ms > 1.f) ? rsqrtf(ms) : 1.f;
        float v = d_pos[i] * sc;
        d_pos[i] = v;
        out[OUT_POS + i] = v;
        float ms2 = d_scal[1];
        float sc2 = (ms2 > 1.f) ? rsqrtf(ms2) : 1.f;
        out[OUT_GEMB + i] = d_gvec[i & (HID - 1)] * (1.f / (float)N_NODES) * sc2;
    }
}

// ---------------- head ------------------------------------------------------
__global__ void k_head(const float* __restrict__ Z, const float* __restrict__ Wl2,
                       const float* __restrict__ bl2, float* __restrict__ out) {
    __shared__ float w[HID * 6];
    int tid = threadIdx.x;
    for (int i = tid; i < HID * 6; i += 128) w[i] = Wl2[i];
    __syncthreads();
    int warp = tid >> 5, lane = tid & 31;
    int row = blockIdx.x * 4 + warp;
    const float* z = Z + (size_t)row * HID;
    float s[6] = {0, 0, 0, 0, 0, 0};
    for (int k = lane; k < HID; k += 32) {
        float zv = z[k];
#pragma unroll
        for (int j = 0; j < 6; ++j) s[j] = fmaf(zv, w[k * 6 + j], s[j]);
    }
#pragma unroll
    for (int o = 16; o > 0; o >>= 1)
#pragma unroll
        for (int j = 0; j < 6; ++j) s[j] += __shfl_xor_sync(0xffffffff, s[j], o);
    if (lane == 0) {
        float o6[6], m = -1e30f;
#pragma unroll
        for (int j = 0; j < 6; ++j) { o6[j] = s[j] + bl2[j]; m = fmaxf(m, o6[j]); }
        float sum = 0.f;
#pragma unroll
        for (int j = 0; j < 6; ++j) sum += expf(o6[j] - m);
        float lse = m + logf(sum);
#pragma unroll
        for (int j = 0; j < 6; ++j) out[OUT_LOGP + row * 6 + j] = o6[j] - lse;
    }
}

// ---------------- launch ----------------------------------------------------
extern "C" void kernel_launch(void* const* d_in, const int* in_sizes, int n_in,
                              void* d_out, int out_size) {
    const float* x   = (const float*)d_in[0];
    const int*   ei  = (const int*)d_in[1];
    const float* W1  = (const float*)d_in[4];
    const float* b1  = (const float*)d_in[5];
    const float* W2  = (const float*)d_in[6];
    const float* b2  = (const float*)d_in[7];
    const float* W3  = (const float*)d_in[8];
    const float* b3  = (const float*)d_in[9];
    const float* Wc1 = (const float*)d_in[10];
    const float* bc1 = (const float*)d_in[11];
    const float* Wc2 = (const float*)d_in[12];
    const float* bc2 = (const float*)d_in[13];
    const float* Wl1 = (const float*)d_in[14];
    const float* bl1 = (const float*)d_in[15];
    const float* Wl2 = (const float*)d_in[16];
    const float* bl2 = (const float*)d_in[17];
    float* out = (float*)d_out;

    float *pT, *pPos;
    __half *pTh, *pHh, *pXh;
    cudaGetSymbolAddress((void**)&pT, d_T);
    cudaGetSymbolAddress((void**)&pPos, d_pos);
    cudaGetSymbolAddress((void**)&pTh, d_Th);
    cudaGetSymbolAddress((void**)&pHh, d_Hh);
    cudaGetSymbolAddress((void**)&pXh, d_Xh);

    cudaFuncSetAttribute(k_aggh, cudaFuncAttributeMaxDynamicSharedMemorySize, AGGH_SMEM);
    cudaFuncSetAttribute(hgemm<FIN, 0>, cudaFuncAttributeMaxDynamicSharedMemorySize, HG_SMEM);
    cudaFuncSetAttribute(hgemm<HID, 0>, cudaFuncAttributeMaxDynamicSharedMemorySize, HG_SMEM);
    cudaFuncSetAttribute(hgemm<HID, 2>, cudaFuncAttributeMaxDynamicSharedMemorySize, HG_SMEM);

    __half* pWh;
    cudaGetSymbolAddress((void**)&pWh, d_Wh);
    __half* Wh0 = pWh;
    __half* Wh1 = pWh + HID * HID;
    __half* Wh2 = pWh + 2 * HID * HID;
    __half* Wh3 = pWh + 3 * HID * HID;

    // fused graph structure build + misc zero + weight prep
    k_zero_misc<<<100, 1024>>>();
    k_build<<<NG, 256>>>(ei);
    k_transpose_all<<<dim3(HID / 32, HID / 32, 4), dim3(32, 8)>>>(W1, W2, W3, Wc1);
    k_x2h<<<(N_NODES * FIN / 2 + 255) / 256, 256>>>((const float2*)x, (__half2*)pXh);

    dim3 gBig(HID / 128, N_NODES / 256);
    dim3 gAgg(NG, 4);

    // 3 GCN layers: T = H@W (fp16 tensor) ; H = A_hat @ T + b (fp16 tensor)
    hgemm<FIN, 0><<<gBig, 256, HG_SMEM>>>(pXh, Wh0, nullptr, pTh, nullptr);
    k_aggh<<<gAgg, 256, AGGH_SMEM>>>(pTh, b1, pHh);
    hgemm<HID, 0><<<gBig, 256, HG_SMEM>>>(pHh, Wh1, nullptr, pTh, nullptr);
    k_aggh<<<gAgg, 256, AGGH_SMEM>>>(pTh, b2, pHh);
    hgemm<HID, 0><<<gBig, 256, HG_SMEM>>>(pHh, Wh2, nullptr, pTh, nullptr);
    k_aggh<<<gAgg, 256, AGGH_SMEM>>>(pTh, b3, pHh);

    // assignment fused into 4th GEMM epilogue, then softmax
    hgemm<HID, 2><<<gBig, 256, HG_SMEM>>>(pHh, Wh3, bc1, pTh, Wc2);
    k_assign2<<<(N_NODES + 255) / 256, 256>>>(bc2);

    // pooling / penalty
    k_pos<<<NG, HID>>>(pHh);
    k_newadj<<<NG, 128>>>(ei);

    // normalizations + final outputs
    k_sumsq_pos<<<256, 256>>>();
    k_pg<<<1, HID>>>();
    k_final<<<1024, 256>>>(out);

    // head MLP on normalized pos (fp32)
    dim3 gHead(HID / 128, NG / 128);
    sgemm<2><<<gHead, 256>>>(pPos, Wl1, bl1, pT, NG, HID, HID);
    k_head<<<NG / 4, 128>>>(pT, Wl2, bl2, out);
}

// round 13
// speedup vs baseline: 1.1032x; 1.0102x over previous
#include <cuda_runtime.h>
#include <cuda_fp16.h>
#include <math.h>
#include <cstdint>

#define N_NODES 51200
#define N_EDGES 819200
#define NG 512
#define NPG 100
#define EPG 1600
#define HID 512
#define FIN 128
#define EPSV 1e-5f

#define OUT_LOGP 0
#define OUT_POS 3072
#define OUT_GEMB 265216
#define OUT_PEN 527360

// ---------------- scratch (static device allocations; no cudaMalloc) --------
__device__ __half d_Ah[NG * 128 * 120];        // padded half adjacency [g][m:128][k:120]
__device__ __half d_Th[N_NODES * HID];         // GEMM output (half)
__device__ __half d_Hh[N_NODES * HID];         // agg output (half)
__device__ __half d_Xh[N_NODES * FIN];         // x in half
__device__ __half d_Wh[4][HID * HID];          // transposed half weights [N][K]
__device__ float d_T[N_NODES * HID];           // fp32 scratch (head path)
__device__ float d_araw[N_NODES * 2];          // raw assignment logits (atomic acc)
__device__ float d_assign[N_NODES * 2];
__device__ float d_pos[NG * HID];
__device__ float d_gvec[HID];
__device__ float d_scal[4];                    // [0]=pos ss, [1]=pg ms, [2]=penalty acc

// ---------------- ptx helpers ----------------------------------------------
__device__ __forceinline__ uint32_t s2u(const void* p) {
    uint32_t a;
    asm("{ .reg .u64 t; cvta.to.shared.u64 t, %1; cvt.u32.u64 %0, t; }"
        : "=r"(a) : "l"(p));
    return a;
}
__device__ __forceinline__ void cp16(uint32_t s, const void* g) {
    asm volatile("cp.async.cg.shared.global [%0], [%1], 16;" :: "r"(s), "l"(g));
}
__device__ __forceinline__ void mma_f16(float* c, const uint32_t* a, const uint32_t* b) {
    asm volatile(
        "mma.sync.aligned.m16n8k16.row.col.f32.f16.f16.f32 "
        "{%0,%1,%2,%3}, {%4,%5,%6,%7}, {%8,%9}, {%0,%1,%2,%3};"
        : "+f"(c[0]), "+f"(c[1]), "+f"(c[2]), "+f"(c[3])
        : "r"(a[0]), "r"(a[1]), "r"(a[2]), "r"(a[3]), "r"(b[0]), "r"(b[1]));
}
__device__ __forceinline__ void ldm4(uint32_t* r, uint32_t addr) {
    asm volatile("ldmatrix.sync.aligned.m8n8.x4.shared.b16 {%0,%1,%2,%3}, [%4];"
                 : "=r"(r[0]), "=r"(r[1]), "=r"(r[2]), "=r"(r[3]) : "r"(addr));
}
__device__ __forceinline__ void ldm4t(uint32_t* r, uint32_t addr) {
    asm volatile("ldmatrix.sync.aligned.m8n8.x4.trans.shared.b16 {%0,%1,%2,%3}, [%4];"
                 : "=r"(r[0]), "=r"(r[1]), "=r"(r[2]), "=r"(r[3]) : "r"(addr));
}

// ---------------- fused per-graph structure build ---------------------------
__global__ void __launch_bounds__(256) k_build(const int* __restrict__ ei) {
    __shared__ float Adj[NPG * NPG];
    __shared__ float deg[NPG];
    __shared__ float dis[NPG];
    int g = blockIdx.x, tid = threadIdx.x;
    for (int i = tid; i < NPG * NPG; i += 256) Adj[i] = 0.f;
    if (tid < NPG) deg[tid] = 0.f;
    __syncthreads();
    const int* src = ei + g * EPG;
    const int* dst = ei + N_EDGES + g * EPG;
    int base = g * NPG;
    for (int e = tid; e < EPG; e += 256) atomicAdd(&deg[dst[e] - base], 1.f);
    __syncthreads();
    if (tid < NPG) dis[tid] = rsqrtf(deg[tid] + 1.f);
    __syncthreads();
    for (int e = tid; e < EPG; e += 256) {
        int s = src[e] - base, d = dst[e] - base;
        atomicAdd(&Adj[d * NPG + s], dis[s] * dis[d]);
    }
    __syncthreads();
    if (tid < NPG) Adj[tid * NPG + tid] += dis[tid] * dis[tid];
    __syncthreads();
    __half2* out = (__half2*)(d_Ah + (size_t)g * 128 * 120);
    for (int i = tid; i < 128 * 60; i += 256) {
        int r = i / 60, k = (i % 60) * 2;
        float v0 = (r < NPG && k < NPG) ? Adj[r * NPG + k] : 0.f;
        float v1 = (r < NPG && k + 1 < NPG) ? Adj[r * NPG + k + 1] : 0.f;
        out[i] = __floats2half2_rn(v0, v1);
    }
}

__global__ void k_zero_misc() {   // grid 100 x 1024
    int i = blockIdx.x * 1024 + threadIdx.x;
    if (i < N_NODES * 2) d_araw[i] = 0.f;
    if (i < HID) d_gvec[i] = 0.f;
    if (i < 4) d_scal[i] = 0.f;
}

// ---------------- fused prep: 4 weight transposes + x->half -----------------
__global__ void k_prep(const float* __restrict__ W1, const float* __restrict__ W2,
                       const float* __restrict__ W3, const float* __restrict__ Wc1,
                       const float4* __restrict__ x) {
    int z = blockIdx.z;
    if (z == 4) {
        // x -> half, 16B reads / 8B writes
        int gid = (blockIdx.y * 16 + blockIdx.x) * 256 + threadIdx.y * 32 + threadIdx.x;
        const int total = N_NODES * FIN / 4;
        uint2* o = (uint2*)d_Xh;
        for (int i = gid; i < total; i += 16 * 16 * 256) {
            float4 v = x[i];
            __half2 h0 = __floats2half2_rn(v.x, v.y);
            __half2 h1 = __floats2half2_rn(v.z, v.w);
            o[i] = make_uint2(*(uint32_t*)&h0, *(uint32_t*)&h1);
        }
        return;
    }
    __shared__ float tile[32][33];
    const float* W = (z == 0) ? W1 : (z == 1) ? W2 : (z == 2) ? W3 : Wc1;
    int K = (z == 0) ? FIN : HID;
    int k0 = blockIdx.y * 32, n0 = blockIdx.x * 32;
    if (k0 >= K) return;
    __half* Wt = d_Wh[z];
    int tx = threadIdx.x, ty = threadIdx.y;
    for (int j = ty; j < 32; j += 8) tile[j][tx] = W[(size_t)(k0 + j) * HID + n0 + tx];
    __syncthreads();
    for (int j = ty; j < 32; j += 8)
        Wt[(size_t)(n0 + j) * K + k0 + tx] = __float2half_rn(tile[tx][j]);
}

// ---------------- fp16 mma GEMM: C[M,512] = A[M,K] @ Wt[512,K]^T ------------
// 256x128 CTA tile, 8 warps as 4x2 (64x64 warp tile), BK=32, 3-stage cp.async,
// single-sync pipeline, ldmatrix fragments.
// EPI: 0 = plain half out, 2 = fused assignment head (tanh + Wc2 dot + atomic)
#define STB_A (256 * 40 * 2)
#define STB_B (128 * 40 * 2)
#define HG_SMEM (3 * (STB_A + STB_B))
template <int K, int EPI>
__global__ void __launch_bounds__(256) hgemm(const __half* __restrict__ A,
                                             const __half* __restrict__ Bt,
                                             const float* __restrict__ bias,
                                             __half* __restrict__ C,
                                             const float* __restrict__ wc2) {
    constexpr int NT = K / 32;
    extern __shared__ __half hsh[];
    __half* As = hsh;                        // 3 x 256*40
    __half* Bs = hsh + 3 * 256 * 40;         // 3 x 128*40
    int tid = threadIdx.x;
    int wid = tid >> 5, lane = tid & 31;
    int g = lane >> 2, q = lane & 3;
    int wm = wid >> 1, wn = wid & 1;
    int m0 = blockIdx.y * 256, n0 = blockIdx.x * 128;

    int lr = tid >> 1, lc = tid & 1;   // row 0..127, half-row chunk
    const __half* Ag0 = A + (size_t)(m0 + lr) * K + lc * 16;
    const __half* Ag1 = A + (size_t)(m0 + lr + 128) * K + lc * 16;
    const __half* Bg = Bt + (size_t)(n0 + lr) * K + lc * 16;
    uint32_t sa0 = s2u(&As[lr * 40 + lc * 16]);
    uint32_t sa1 = s2u(&As[(lr + 128) * 40 + lc * 16]);
    uint32_t sb = s2u(&Bs[lr * 40 + lc * 16]);

    auto load_stage = [&](int kt, int st) {
        uint32_t oA = st * STB_A, oB = st * STB_B;
        cp16(sa0 + oA, Ag0 + kt * 32);
        cp16(sa0 + oA + 16, Ag0 + kt * 32 + 8);
        cp16(sa1 + oA, Ag1 + kt * 32);
        cp16(sa1 + oA + 16, Ag1 + kt * 32 + 8);
        cp16(sb + oB, Bg + kt * 32);
        cp16(sb + oB + 16, Bg + kt * 32 + 8);
        asm volatile("cp.async.commit_group;" ::: "memory");
    };

    uint32_t AsU = s2u(As), BsU = s2u(Bs);
    int laneA = (wm * 64 + (lane & 15)) * 40 + ((lane >> 4) & 1) * 8;
    int laneB = (wn * 64 + ((lane >> 4) & 1) * 8 + (lane & 7)) * 40
                + ((lane >> 3) & 1) * 8;

    float acc[4][8][4];
#pragma unroll
    for (int i = 0; i < 4; ++i)
#pragma unroll
        for (int j = 0; j < 8; ++j)
#pragma unroll
            for (int t = 0; t < 4; ++t) acc[i][j][t] = 0.f;

    load_stage(0, 0);
    if (NT > 1) load_stage(1, 1);

#pragma unroll 1
    for (int kt = 0; kt < NT; ++kt) {
        if (kt + 1 < NT) asm volatile("cp.async.wait_group 1;" ::: "memory");
        else             asm volatile("cp.async.wait_group 0;" ::: "memory");
        __syncthreads();
        if (kt + 2 < NT) load_stage(kt + 2, (kt + 2) % 3);

        uint32_t soA = (kt % 3) * STB_A, soB = (kt % 3) * STB_B;
#pragma unroll
        for (int ks = 0; ks < 2; ++ks) {
            uint32_t ko = ks * 32;   // bytes (16 halves)
            uint32_t af[4][4];
#pragma unroll
            for (int mi = 0; mi < 4; ++mi)
                ldm4(af[mi], AsU + soA + (laneA + mi * 16 * 40) * 2 + ko);
#pragma unroll
            for (int p = 0; p < 4; ++p) {
                uint32_t bf[4];
                ldm4(bf, BsU + soB + (laneB + p * 16 * 40) * 2 + ko);
#pragma unroll
                for (int mi = 0; mi < 4; ++mi) {
                    mma_f16(acc[mi][2 * p], af[mi], bf);
                    mma_f16(acc[mi][2 * p + 1], af[mi], bf + 2);
                }
            }
        }
    }

    if (EPI == 0) {
#pragma unroll
        for (int mi = 0; mi < 4; ++mi) {
            int row0 = m0 + wm * 64 + mi * 16 + g;
#pragma unroll
            for (int ni = 0; ni < 8; ++ni) {
                int col = n0 + wn * 64 + ni * 8 + 2 * q;
                *(half2*)(C + (size_t)row0 * HID + col) =
                    __floats2half2_rn(acc[mi][ni][0], acc[mi][ni][1]);
                *(half2*)(C + (size_t)(row0 + 8) * HID + col) =
                    __floats2half2_rn(acc[mi][ni][2], acc[mi][ni][3]);
            }
        }
    } else {
        // fused assignment head: s = sum_col tanh(acc+bc1[col]) * Wc2[col][:]
        float s[4][2][2];
#pragma unroll
        for (int mi = 0; mi < 4; ++mi)
#pragma unroll
            for (int r = 0; r < 2; ++r) { s[mi][r][0] = 0.f; s[mi][r][1] = 0.f; }
#pragma unroll
        for (int ni = 0; ni < 8; ++ni) {
            int col = n0 + wn * 64 + ni * 8 + 2 * q;
            float4 w4 = *(const float4*)(wc2 + col * 2);
            float2 bb = *(const float2*)(bias + col);
#pragma unroll
            for (int mi = 0; mi < 4; ++mi) {
                float v0 = tanhf(acc[mi][ni][0] + bb.x);
                float v1 = tanhf(acc[mi][ni][1] + bb.y);
                float v2 = tanhf(acc[mi][ni][2] + bb.x);
                float v3 = tanhf(acc[mi][ni][3] + bb.y);
                s[mi][0][0] += v0 * w4.x + v1 * w4.z;
                s[mi][0][1] += v0 * w4.y + v1 * w4.w;
                s[mi][1][0] += v2 * w4.x + v3 * w4.z;
                s[mi][1][1] += v2 * w4.y + v3 * w4.w;
            }
        }
#pragma unroll
        for (int mi = 0; mi < 4; ++mi)
#pragma unroll
            for (int r = 0; r < 2; ++r)
#pragma unroll
                for (int c = 0; c < 2; ++c) {
                    float v = s[mi][r][c];
                    v += __shfl_xor_sync(0xffffffff, v, 1);
                    v += __shfl_xor_sync(0xffffffff, v, 2);
                    s[mi][r][c] = v;
                }
        if (q == 0) {
#pragma unroll
            for (int mi = 0; mi < 4; ++mi)
#pragma unroll
                for (int r = 0; r < 2; ++r) {
                    int row = m0 + wm * 64 + mi * 16 + g + r * 8;
                    atomicAdd(&d_araw[row * 2], s[mi][r][0]);
                    atomicAdd(&d_araw[row * 2 + 1], s[mi][r][1]);
                }
        }
    }
}

// ---------------- tensor-core agg: H = A_g @ T_g + b ------------------------
// Ts stored [k:112][n:128] (row stride 136 halves), B frags via ldmatrix.trans.
// Grid (NG, 4), warps 2x2 (32 rows x 64 cols each). R9-proven configuration.
#define TS_LD 136
#define AGGH_SMEM ((128 * 120 + 112 * TS_LD) * 2)
__global__ void __launch_bounds__(256) k_aggh(const __half* __restrict__ T,
                                              const float* __restrict__ bias,
                                              __half* __restrict__ Hh) {
    extern __shared__ __half aggsh[];
    __half* Ash = aggsh;                   // [128][120]
    __half* Ts = aggsh + 128 * 120;        // [112][136]
    int gph = blockIdx.x;
    int cb = blockIdx.y * 128;
    int tid = threadIdx.x;
    int wid = tid >> 5, lane = tid & 31;
    int g = lane >> 2, q = lane & 3;
    int wm = wid >> 1, wn = wid & 1;

    const uint4* Asrc = (const uint4*)(d_Ah + (size_t)gph * 128 * 120);
    uint4* Adst = (uint4*)Ash;
    for (int i = tid; i < 128 * 120 / 8; i += 256) Adst[i] = Asrc[i];

    // Ts[k][n] direct copy: 16 x uint4 (=128 halves) per row, zero pad k 100..111
    const __half* Tg = T + (size_t)gph * NPG * HID + cb;
    const uint4 z4 = make_uint4(0, 0, 0, 0);
    for (int i = tid; i < 112 * 16; i += 256) {
        int k = i >> 4, c = i & 15;
        uint4 v = (k < NPG) ? *(const uint4*)(Tg + (size_t)k * HID + c * 8) : z4;
        *(uint4*)(Ts + k * TS_LD + c * 8) = v;
    }
    __syncthreads();

    uint32_t AshU = s2u(Ash), TsU = s2u(Ts);
    int laneA = (wm * 32 + (lane & 15)) * 120 + ((lane >> 4) & 1) * 8;
    int laneBt = (lane & 15) * TS_LD + wn * 64 + ((lane >> 4) & 1) * 8;

    float acc[2][8][4];
#pragma unroll
    for (int i = 0; i < 2; ++i)
#pragma unroll
        for (int j = 0; j < 8; ++j)
#pragma unroll
            for (int t = 0; t < 4; ++t) acc[i][j][t] = 0.f;

#pragma unroll
    for (int k0 = 0; k0 < 112; k0 += 16) {
        uint32_t af[2][4];
#pragma unroll
        for (int mi = 0; mi < 2; ++mi)
            ldm4(af[mi], AshU + (laneA + mi * 16 * 120 + k0) * 2);
#pragma unroll
        for (int p = 0; p < 4; ++p) {
            uint32_t bf[4];
            ldm4t(bf, TsU + (laneBt + k0 * TS_LD + p * 16) * 2);
#pragma unroll
            for (int mi = 0; mi < 2; ++mi) {
                mma_f16(acc[mi][2 * p], af[mi], bf);
                mma_f16(acc[mi][2 * p + 1], af[mi], bf + 2);
            }
        }
    }

#pragma unroll
    for (int mi = 0; mi < 2; ++mi) {
        int rl = wm * 32 + mi * 16 + g;
#pragma unroll
        for (int ni = 0; ni < 8; ++ni) {
            int col = cb + wn * 64 + ni * 8 + 2 * q;
            float2 bb = *(const float2*)(bias + col);
            if (rl < NPG) {
                size_t off = ((size_t)gph * NPG + rl) * HID + col;
                *(half2*)(Hh + off) =
                    __floats2half2_rn(acc[mi][ni][0] + bb.x, acc[mi][ni][1] + bb.y);
            }
            if (rl + 8 < NPG) {
                size_t off = ((size_t)gph * NPG + rl + 8) * HID + col;
                *(half2*)(Hh + off) =
                    __floats2half2_rn(acc[mi][ni][2] + bb.x, acc[mi][ni][3] + bb.y);
            }
        }
    }
}

// ---------------- fp32 tiled SGEMM (head only) ------------------------------
template <int EPI>
__global__ void sgemm(const float* __restrict__ A, const float* __restrict__ B,
                      const float* __restrict__ bias, float* __restrict__ C,
                      int M, int N, int K) {
    __shared__ float As[8][128];
    __shared__ float Bs[8][128];
    int tid = threadIdx.x;
    int m0 = blockIdx.y * 128;
    int n0 = blockIdx.x * 128;
    int arow = tid >> 1;
    int acol = (tid & 1) * 4;
    int brow = tid >> 5;
    int bcol = (tid & 31) * 4;
    int ty = tid >> 4;
    int tx = tid & 15;
    float acc[8][8] = {};

    for (int k0 = 0; k0 < K; k0 += 8) {
        float4 av = *(const float4*)(A + (size_t)(m0 + arow) * K + k0 + acol);
        As[acol + 0][arow] = av.x;
        As[acol + 1][arow] = av.y;
        As[acol + 2][arow] = av.z;
        As[acol + 3][arow] = av.w;
        *(float4*)(&Bs[brow][bcol]) =
            *(const float4*)(B + (size_t)(k0 + brow) * N + n0 + bcol);
        __syncthreads();
#pragma unroll
        for (int k = 0; k < 8; ++k) {
            float a[8], b[8];
            *(float4*)(a) = *(float4*)(&As[k][ty * 8]);
            *(float4*)(a + 4) = *(float4*)(&As[k][ty * 8 + 4]);
            *(float4*)(b) = *(float4*)(&Bs[k][tx * 8]);
            *(float4*)(b + 4) = *(float4*)(&Bs[k][tx * 8 + 4]);
#pragma unroll
            for (int i = 0; i < 8; ++i)
#pragma unroll
                for (int j = 0; j < 8; ++j) acc[i][j] = fmaf(a[i], b[j], acc[i][j]);
        }
        __syncthreads();
    }
#pragma unroll
    for (int i = 0; i < 8; ++i) {
        int row = m0 + ty * 8 + i;
#pragma unroll
        for (int j = 0; j < 8; j += 4) {
            int col = n0 + tx * 8 + j;
            float4 v = make_float4(acc[i][j], acc[i][j + 1], acc[i][j + 2], acc[i][j + 3]);
            if (EPI != 0) {
                float4 bb = *(const float4*)(bias + col);
                v.x += bb.x; v.y += bb.y; v.z += bb.z; v.w += bb.w;
                if (EPI == 1) {
                    v.x = tanhf(v.x); v.y = tanhf(v.y); v.z = tanhf(v.z); v.w = tanhf(v.w);
                } else {
                    v.x = fmaxf(v.x, 0.f); v.y = fmaxf(v.y, 0.f);
                    v.z = fmaxf(v.z, 0.f); v.w = fmaxf(v.w, 0.f);
                }
            }
            *(float4*)(C + (size_t)row * N + col) = v;
        }
    }
}

// ---------------- pos + assignment softmax + global h column sums -----------
__global__ void k_pos(const __half* __restrict__ H, const float* __restrict__ bc2) {
    __shared__ float a0[NPG];
    int g = blockIdx.x, c = threadIdx.x;   // 512 threads
    if (c < NPG) {
        int n = g * NPG + c;
        float z0 = d_araw[2 * n] + bc2[0], z1 = d_araw[2 * n + 1] + bc2[1];
        float m = fmaxf(z0, z1);
        float e0 = expf(z0 - m), e1 = expf(z1 - m);
        float inv = 1.f / (e0 + e1);
        float s0 = e0 * inv;
        a0[c] = s0;
        d_assign[2 * n] = s0;
        d_assign[2 * n + 1] = e1 * inv;
    }
    __syncthreads();
    const __half* h = H + (size_t)g * NPG * HID;
    float acc = 0.f, gs = 0.f;
    for (int n = 0; n < NPG; ++n) {
        float hv = __half2float(h[n * HID + c]);
        acc = fmaf(a0[n], hv, acc);
        gs += hv;
    }
    d_pos[g * HID + c] = acc;
    atomicAdd(&d_gvec[c], gs);
}

// ---------------- new_adj + penalty (fused, per-graph atomic) ---------------
__global__ void k_newadj(const int* __restrict__ ei) {
    __shared__ float sa[NPG * 2];
    __shared__ float red[4][4];
    int g = blockIdx.x, tid = threadIdx.x;
    if (tid < NPG * 2) sa[tid] = d_assign[g * NPG * 2 + tid];
    __syncthreads();
    float a00 = 0, a01 = 0, a10 = 0, a11 = 0;
    for (int e = tid; e < EPG; e += 128) {
        int s = ei[g * EPG + e] - g * NPG;
        int d = ei[N_EDGES + g * EPG + e] - g * NPG;
        float s0 = sa[2 * s], s1 = sa[2 * s + 1];
        float t0 = sa[2 * d], t1 = sa[2 * d + 1];
        a00 = fmaf(s0, t0, a00); a01 = fmaf(s0, t1, a01);
        a10 = fmaf(s1, t0, a10); a11 = fmaf(s1, t1, a11);
    }
#pragma unroll
    for (int o = 16; o > 0; o >>= 1) {
        a00 += __shfl_xor_sync(0xffffffff, a00, o);
        a01 += __shfl_xor_sync(0xffffffff, a01, o);
        a10 += __shfl_xor_sync(0xffffffff, a10, o);
        a11 += __shfl_xor_sync(0xffffffff, a11, o);
    }
    int warp = tid >> 5, lane = tid & 31;
    if (lane == 0) {
        red[warp][0] = a00; red[warp][1] = a01;
        red[warp][2] = a10; red[warp][3] = a11;
    }
    __syncthreads();
    if (tid == 0) {
        float v00 = red[0][0] + red[1][0] + red[2][0] + red[3][0];
        float v01 = red[0][1] + red[1][1] + red[2][1] + red[3][1];
        float v10 = red[0][2] + red[1][2] + red[2][2] + red[3][2];
        float v11 = red[0][3] + red[1][3] + red[2][3] + red[3][3];
        float r0 = fmaxf(fabsf(v00) + fabsf(v01), EPSV);
        float r1 = fmaxf(fabsf(v10) + fabsf(v11), EPSV);
        float dd0 = v00 / r0 - 1.f, dd1 = v11 / r1 - 1.f;
        atomicAdd(&d_scal[2], dd0 * dd0 + dd1 * dd1);
    }
}

// ---------------- merged norm reductions ------------------------------------
__global__ void k_norm() {
    __shared__ float red[256];
    int tid = threadIdx.x;
    if (blockIdx.x < 256) {
        float s = 0.f;
        for (int i = blockIdx.x * 256 + tid; i < NG * HID; i += 256 * 256) {
            float v = d_pos[i];
            s = fmaf(v, v, s);
        }
        red[tid] = s;
        __syncthreads();
        for (int o = 128; o > 0; o >>= 1) {
            if (tid < o) red[tid] += red[tid + o];
            __syncthreads();
        }
        if (tid == 0) atomicAdd(&d_scal[0], red[0]);
    } else {
        float v0 = d_gvec[tid] * (1.f / (float)N_NODES);
        float v1 = d_gvec[tid + 256] * (1.f / (float)N_NODES);
        red[tid] = v0 * v0 + v1 * v1;
        __syncthreads();
        for (int o = 128; o > 0; o >>= 1) {
            if (tid < o) red[tid] += red[tid + o];
            __syncthreads();
        }
        if (tid == 0) d_scal[1] = red[0] * (1.f / (float)HID);
    }
}

// ---------------- final outputs: pos, gemb, penalty -------------------------
__global__ void k_final(float* __restrict__ out) {
    int i = blockIdx.x * blockDim.x + threadIdx.x;
    if (i == 0) out[OUT_PEN] = d_scal[2] * (1.f / (NG * 2.f));
    if (i < NG * HID) {
        float ms = d_scal[0] * (1.f / (float)(NG * HID));
        float sc = (ms > 1.f) ? rsqrtf(ms) : 1.f;
        float v = d_pos[i] * sc;
        d_pos[i] = v;
        out[OUT_POS + i] = v;
        float ms2 = d_scal[1];
        float sc2 = (ms2 > 1.f) ? rsqrtf(ms2) : 1.f;
        out[OUT_GEMB + i] = d_gvec[i & (HID - 1)] * (1.f / (float)N_NODES) * sc2;
    }
}

// ---------------- head ------------------------------------------------------
__global__ void k_head(const float* __restrict__ Z, const float* __restrict__ Wl2,
                       const float* __restrict__ bl2, float* __restrict__ out) {
    __shared__ float w[HID * 6];
    int tid = threadIdx.x;
    for (int i = tid; i < HID * 6; i += 128) w[i] = Wl2[i];
    __syncthreads();
    int warp = tid >> 5, lane = tid & 31;
    int row = blockIdx.x * 4 + warp;
    const float* z = Z + (size_t)row * HID;
    float s[6] = {0, 0, 0, 0, 0, 0};
    for (int k = lane; k < HID; k += 32) {
        float zv = z[k];
#pragma unroll
        for (int j = 0; j < 6; ++j) s[j] = fmaf(zv, w[k * 6 + j], s[j]);
    }
#pragma unroll
    for (int o = 16; o > 0; o >>= 1)
#pragma unroll
        for (int j = 0; j < 6; ++j) s[j] += __shfl_xor_sync(0xffffffff, s[j], o);
    if (lane == 0) {
        float o6[6], m = -1e30f;
#pragma unroll
        for (int j = 0; j < 6; ++j) { o6[j] = s[j] + bl2[j]; m = fmaxf(m, o6[j]); }
        float sum = 0.f;
#pragma unroll
        for (int j = 0; j < 6; ++j) sum += expf(o6[j] - m);
        float lse = m + logf(sum);
#pragma unroll
        for (int j = 0; j < 6; ++j) out[OUT_LOGP + row * 6 + j] = o6[j] - lse;
    }
}

// ---------------- launch ----------------------------------------------------
extern "C" void kernel_launch(void* const* d_in, const int* in_sizes, int n_in,
                              void* d_out, int out_size) {
    const float* x   = (const float*)d_in[0];
    const int*   ei  = (const int*)d_in[1];
    const float* W1  = (const float*)d_in[4];
    const float* b1  = (const float*)d_in[5];
    const float* W2  = (const float*)d_in[6];
    const float* b2  = (const float*)d_in[7];
    const float* W3  = (const float*)d_in[8];
    const float* b3  = (const float*)d_in[9];
    const float* Wc1 = (const float*)d_in[10];
    const float* bc1 = (const float*)d_in[11];
    const float* Wc2 = (const float*)d_in[12];
    const float* bc2 = (const float*)d_in[13];
    const float* Wl1 = (const float*)d_in[14];
    const float* bl1 = (const float*)d_in[15];
    const float* Wl2 = (const float*)d_in[16];
    const float* bl2 = (const float*)d_in[17];
    float* out = (float*)d_out;

    float *pT, *pPos;
    __half *pTh, *pHh, *pXh, *pWh;
    cudaGetSymbolAddress((void**)&pT, d_T);
    cudaGetSymbolAddress((void**)&pPos, d_pos);
    cudaGetSymbolAddress((void**)&pTh, d_Th);
    cudaGetSymbolAddress((void**)&pHh, d_Hh);
    cudaGetSymbolAddress((void**)&pXh, d_Xh);
    cudaGetSymbolAddress((void**)&pWh, d_Wh);

    cudaFuncSetAttribute(k_aggh, cudaFuncAttributeMaxDynamicSharedMemorySize, AGGH_SMEM);
    cudaFuncSetAttribute(hgemm<FIN, 0>, cudaFuncAttributeMaxDynamicSharedMemorySize, HG_SMEM);
    cudaFuncSetAttribute(hgemm<HID, 0>, cudaFuncAttributeMaxDynamicSharedMemorySize, HG_SMEM);
    cudaFuncSetAttribute(hgemm<HID, 2>, cudaFuncAttributeMaxDynamicSharedMemorySize, HG_SMEM);

    __half* Wh0 = pWh;
    __half* Wh1 = pWh + HID * HID;
    __half* Wh2 = pWh + 2 * HID * HID;
    __half* Wh3 = pWh + 3 * HID * HID;

    // prep: zero, graph build, transposes + x->half (fused)
    k_zero_misc<<<100, 1024>>>();
    k_build<<<NG, 256>>>(ei);
    k_prep<<<dim3(16, 16, 5), dim3(32, 8)>>>(W1, W2, W3, Wc1, (const float4*)x);

    dim3 gBig(HID / 128, N_NODES / 256);
    dim3 gAgg(NG, 4);

    // 3 GCN layers: T = H@W (fp16 tensor) ; H = A_hat @ T + b (fp16 tensor)
    hgemm<FIN, 0><<<gBig, 256, HG_SMEM>>>(pXh, Wh0, nullptr, pTh, nullptr);
    k_aggh<<<gAgg, 256, AGGH_SMEM>>>(pTh, b1, pHh);
    hgemm<HID, 0><<<gBig, 256, HG_SMEM>>>(pHh, Wh1, nullptr, pTh, nullptr);
    k_aggh<<<gAgg, 256, AGGH_SMEM>>>(pTh, b2, pHh);
    hgemm<HID, 0><<<gBig, 256, HG_SMEM>>>(pHh, Wh2, nullptr, pTh, nullptr);
    k_aggh<<<gAgg, 256, AGGH_SMEM>>>(pTh, b3, pHh);

    // assignment fused into 4th GEMM epilogue
    hgemm<HID, 2><<<gBig, 256, HG_SMEM>>>(pHh, Wh3, bc1, pTh, Wc2);

    // pooling (with fused assignment softmax) / penalty
    k_pos<<<NG, HID>>>(pHh, bc2);
    k_newadj<<<NG, 128>>>(ei);

    // normalizations + final outputs
    k_norm<<<257, 256>>>();
    k_final<<<1024, 256>>>(out);

    // head MLP on normalized pos (fp32)
    dim3 gHead(HID / 128, NG / 128);
    sgemm<2><<<gHead, 256>>>(pPos, Wl1, bl1, pT, NG, HID, HID);
    k_head<<<NG / 4, 128>>>(pT, Wl2, bl2, out);
}

// round 14
// speedup vs baseline: 1.2042x; 1.0916x over previous
#include <cuda_runtime.h>
#include <cuda_fp16.h>
#include <math.h>
#include <cstdint>

#define N_NODES 51200
#define N_EDGES 819200
#define NG 512
#define NPG 100
#define EPG 1600
#define HID 512
#define FIN 128
#define EPSV 1e-5f

#define OUT_LOGP 0
#define OUT_POS 3072
#define OUT_GEMB 265216
#define OUT_PEN 527360

// ---------------- scratch (static device allocations; no cudaMalloc) --------
__device__ __half d_Ah[NG * 128 * 120];        // padded half adjacency [g][m:128][k:120]
__device__ __half d_Th[N_NODES * HID];         // GEMM output (half)
__device__ __half d_Hh[N_NODES * HID];         // agg output (half)
__device__ __half d_Xh[N_NODES * FIN];         // x in half
__device__ __half d_Wh[4][HID * HID];          // transposed half weights [N][K]
__device__ float d_T[N_NODES * HID];           // fp32 scratch (head path)
__device__ float d_araw[N_NODES * 2];          // raw assignment logits (atomic acc)
__device__ float d_assign[N_NODES * 2];
__device__ float d_pos[NG * HID];
__device__ float d_gvec[HID];
__device__ float d_scal[4];                    // [0]=pos ss, [1]=pg ms, [2]=penalty acc

// ---------------- ptx helpers ----------------------------------------------
__device__ __forceinline__ uint32_t s2u(const void* p) {
    uint32_t a;
    asm("{ .reg .u64 t; cvta.to.shared.u64 t, %1; cvt.u32.u64 %0, t; }"
        : "=r"(a) : "l"(p));
    return a;
}
__device__ __forceinline__ void cp16(uint32_t s, const void* g) {
    asm volatile("cp.async.cg.shared.global [%0], [%1], 16;" :: "r"(s), "l"(g));
}
__device__ __forceinline__ void mma_f16(float* c, const uint32_t* a, const uint32_t* b) {
    asm volatile(
        "mma.sync.aligned.m16n8k16.row.col.f32.f16.f16.f32 "
        "{%0,%1,%2,%3}, {%4,%5,%6,%7}, {%8,%9}, {%0,%1,%2,%3};"
        : "+f"(c[0]), "+f"(c[1]), "+f"(c[2]), "+f"(c[3])
        : "r"(a[0]), "r"(a[1]), "r"(a[2]), "r"(a[3]), "r"(b[0]), "r"(b[1]));
}
__device__ __forceinline__ void ldm4(uint32_t* r, uint32_t addr) {
    asm volatile("ldmatrix.sync.aligned.m8n8.x4.shared.b16 {%0,%1,%2,%3}, [%4];"
                 : "=r"(r[0]), "=r"(r[1]), "=r"(r[2]), "=r"(r[3]) : "r"(addr));
}
__device__ __forceinline__ void ldm4t(uint32_t* r, uint32_t addr) {
    asm volatile("ldmatrix.sync.aligned.m8n8.x4.trans.shared.b16 {%0,%1,%2,%3}, [%4];"
                 : "=r"(r[0]), "=r"(r[1]), "=r"(r[2]), "=r"(r[3]) : "r"(addr));
}

// ---------------- fused per-graph structure build ---------------------------
__global__ void __launch_bounds__(256) k_build(const int* __restrict__ ei) {
    __shared__ float Adj[NPG * NPG];
    __shared__ float deg[NPG];
    __shared__ float dis[NPG];
    int g = blockIdx.x, tid = threadIdx.x;
    for (int i = tid; i < NPG * NPG; i += 256) Adj[i] = 0.f;
    if (tid < NPG) deg[tid] = 0.f;
    __syncthreads();
    const int* src = ei + g * EPG;
    const int* dst = ei + N_EDGES + g * EPG;
    int base = g * NPG;
    for (int e = tid; e < EPG; e += 256) atomicAdd(&deg[dst[e] - base], 1.f);
    __syncthreads();
    if (tid < NPG) dis[tid] = rsqrtf(deg[tid] + 1.f);
    __syncthreads();
    for (int e = tid; e < EPG; e += 256) {
        int s = src[e] - base, d = dst[e] - base;
        atomicAdd(&Adj[d * NPG + s], dis[s] * dis[d]);
    }
    __syncthreads();
    if (tid < NPG) Adj[tid * NPG + tid] += dis[tid] * dis[tid];
    __syncthreads();
    __half2* out = (__half2*)(d_Ah + (size_t)g * 128 * 120);
    for (int i = tid; i < 128 * 60; i += 256) {
        int r = i / 60, k = (i % 60) * 2;
        float v0 = (r < NPG && k < NPG) ? Adj[r * NPG + k] : 0.f;
        float v1 = (r < NPG && k + 1 < NPG) ? Adj[r * NPG + k + 1] : 0.f;
        out[i] = __floats2half2_rn(v0, v1);
    }
}

__global__ void k_zero_misc() {   // grid 100 x 1024
    int i = blockIdx.x * 1024 + threadIdx.x;
    if (i < N_NODES * 2) d_araw[i] = 0.f;
    if (i < HID) d_gvec[i] = 0.f;
    if (i < 4) d_scal[i] = 0.f;
}

// ---------------- fused prep: 4 weight transposes + x->half -----------------
__global__ void k_prep(const float* __restrict__ W1, const float* __restrict__ W2,
                       const float* __restrict__ W3, const float* __restrict__ Wc1,
                       const float4* __restrict__ x) {
    int z = blockIdx.z;
    if (z == 4) {
        int gid = (blockIdx.y * 16 + blockIdx.x) * 256 + threadIdx.y * 32 + threadIdx.x;
        const int total = N_NODES * FIN / 4;
        uint2* o = (uint2*)d_Xh;
        for (int i = gid; i < total; i += 16 * 16 * 256) {
            float4 v = x[i];
            __half2 h0 = __floats2half2_rn(v.x, v.y);
            __half2 h1 = __floats2half2_rn(v.z, v.w);
            o[i] = make_uint2(*(uint32_t*)&h0, *(uint32_t*)&h1);
        }
        return;
    }
    __shared__ float tile[32][33];
    const float* W = (z == 0) ? W1 : (z == 1) ? W2 : (z == 2) ? W3 : Wc1;
    int K = (z == 0) ? FIN : HID;
    int k0 = blockIdx.y * 32, n0 = blockIdx.x * 32;
    if (k0 >= K) return;
    __half* Wt = d_Wh[z];
    int tx = threadIdx.x, ty = threadIdx.y;
    for (int j = ty; j < 32; j += 8) tile[j][tx] = W[(size_t)(k0 + j) * HID + n0 + tx];
    __syncthreads();
    for (int j = ty; j < 32; j += 8)
        Wt[(size_t)(n0 + j) * K + k0 + tx] = __float2half_rn(tile[tx][j]);
}

// ---------------- fp16 mma GEMM: C[M,512] = A[M,K] @ Wt[512,K]^T ------------
// 128x128 CTA tile, 8 warps as 2x4 (64x32 warp tile), BK=32, 3-stage cp.async,
// single-sync pipeline, ldmatrix fragments, occupancy 2 (regs <= 128).
// EPI: 0 = plain half out, 2 = fused assignment head (tanh + Wc2 dot + atomic)
#define STB (128 * 40 * 2)
#define HG_SMEM (3 * 2 * STB)
template <int K, int EPI>
__global__ void __launch_bounds__(256, 2) hgemm(const __half* __restrict__ A,
                                                const __half* __restrict__ Bt,
                                                const float* __restrict__ bias,
                                                __half* __restrict__ C,
                                                const float* __restrict__ wc2) {
    constexpr int NT = K / 32;
    extern __shared__ __half hsh[];
    __half* As = hsh;                 // 3 x 128*40
    __half* Bs = hsh + 3 * 128 * 40;  // 3 x 128*40
    int tid = threadIdx.x;
    int wid = tid >> 5, lane = tid & 31;
    int g = lane >> 2, q = lane & 3;
    int wm = wid >> 2, wn = wid & 3;
    int m0 = blockIdx.y * 128, n0 = blockIdx.x * 128;

    int lr = tid >> 1, lc = tid & 1;   // row 0..127, 16-half chunk
    const __half* Ag = A + (size_t)(m0 + lr) * K + lc * 16;
    const __half* Bg = Bt + (size_t)(n0 + lr) * K + lc * 16;
    uint32_t sa = s2u(&As[lr * 40 + lc * 16]);
    uint32_t sb = s2u(&Bs[lr * 40 + lc * 16]);

    auto load_stage = [&](int kt, int st) {
        uint32_t o = st * STB;
        cp16(sa + o, Ag + kt * 32);
        cp16(sa + o + 16, Ag + kt * 32 + 8);
        cp16(sb + o, Bg + kt * 32);
        cp16(sb + o + 16, Bg + kt * 32 + 8);
        asm volatile("cp.async.commit_group;" ::: "memory");
    };

    uint32_t AsU = s2u(As), BsU = s2u(Bs);
    int laneA = (wm * 64 + (lane & 15)) * 40 + ((lane >> 4) & 1) * 8;
    int laneB = (wn * 32 + ((lane >> 4) & 1) * 8 + (lane & 7)) * 40
                + ((lane >> 3) & 1) * 8;

    float acc[4][4][4];
#pragma unroll
    for (int i = 0; i < 4; ++i)
#pragma unroll
        for (int j = 0; j < 4; ++j)
#pragma unroll
            for (int t = 0; t < 4; ++t) acc[i][j][t] = 0.f;

    load_stage(0, 0);
    if (NT > 1) load_stage(1, 1);

#pragma unroll 1
    for (int kt = 0; kt < NT; ++kt) {
        if (kt + 1 < NT) asm volatile("cp.async.wait_group 1;" ::: "memory");
        else             asm volatile("cp.async.wait_group 0;" ::: "memory");
        __syncthreads();
        if (kt + 2 < NT) load_stage(kt + 2, (kt + 2) % 3);

        uint32_t so = (kt % 3) * STB;
#pragma unroll
        for (int ks = 0; ks < 2; ++ks) {
            uint32_t ko = ks * 32;   // bytes (16 halves)
            uint32_t af[4][4];
#pragma unroll
            for (int mi = 0; mi < 4; ++mi)
                ldm4(af[mi], AsU + so + (laneA + mi * 16 * 40) * 2 + ko);
#pragma unroll
            for (int p = 0; p < 2; ++p) {
                uint32_t bf[4];
                ldm4(bf, BsU + so + (laneB + p * 16 * 40) * 2 + ko);
#pragma unroll
                for (int mi = 0; mi < 4; ++mi) {
                    mma_f16(acc[mi][2 * p], af[mi], bf);
                    mma_f16(acc[mi][2 * p + 1], af[mi], bf + 2);
                }
            }
        }
    }

    if (EPI == 0) {
#pragma unroll
        for (int mi = 0; mi < 4; ++mi) {
            int row0 = m0 + wm * 64 + mi * 16 + g;
#pragma unroll
            for (int ni = 0; ni < 4; ++ni) {
                int col = n0 + wn * 32 + ni * 8 + 2 * q;
                *(half2*)(C + (size_t)row0 * HID + col) =
                    __floats2half2_rn(acc[mi][ni][0], acc[mi][ni][1]);
                *(half2*)(C + (size_t)(row0 + 8) * HID + col) =
                    __floats2half2_rn(acc[mi][ni][2], acc[mi][ni][3]);
            }
        }
    } else {
        // fused assignment head: s = sum_col tanh(acc+bc1[col]) * Wc2[col][:]
        float s[4][2][2];
#pragma unroll
        for (int mi = 0; mi < 4; ++mi)
#pragma unroll
            for (int r = 0; r < 2; ++r) { s[mi][r][0] = 0.f; s[mi][r][1] = 0.f; }
#pragma unroll
        for (int ni = 0; ni < 4; ++ni) {
            int col = n0 + wn * 32 + ni * 8 + 2 * q;
            float4 w4 = *(const float4*)(wc2 + col * 2);
            float2 bb = *(const float2*)(bias + col);
#pragma unroll
            for (int mi = 0; mi < 4; ++mi) {
                float v0 = tanhf(acc[mi][ni][0] + bb.x);
                float v1 = tanhf(acc[mi][ni][1] + bb.y);
                float v2 = tanhf(acc[mi][ni][2] + bb.x);
                float v3 = tanhf(acc[mi][ni][3] + bb.y);
                s[mi][0][0] += v0 * w4.x + v1 * w4.z;
                s[mi][0][1] += v0 * w4.y + v1 * w4.w;
                s[mi][1][0] += v2 * w4.x + v3 * w4.z;
                s[mi][1][1] += v2 * w4.y + v3 * w4.w;
            }
        }
#pragma unroll
        for (int mi = 0; mi < 4; ++mi)
#pragma unroll
            for (int r = 0; r < 2; ++r)
#pragma unroll
                for (int c = 0; c < 2; ++c) {
                    float v = s[mi][r][c];
                    v += __shfl_xor_sync(0xffffffff, v, 1);
                    v += __shfl_xor_sync(0xffffffff, v, 2);
                    s[mi][r][c] = v;
                }
        if (q == 0) {
#pragma unroll
            for (int mi = 0; mi < 4; ++mi)
#pragma unroll
                for (int r = 0; r < 2; ++r) {
                    int row = m0 + wm * 64 + mi * 16 + g + r * 8;
                    atomicAdd(&d_araw[row * 2], s[mi][r][0]);
                    atomicAdd(&d_araw[row * 2 + 1], s[mi][r][1]);
                }
        }
    }
}

// ---------------- tensor-core agg: H = A_g @ T_g + b ------------------------
// Ts stored [k:112][n:128] (row stride 136 halves), B frags via ldmatrix.trans.
// Grid (NG, 4), warps 2x2 (32 rows x 64 cols each). R9-proven configuration.
#define TS_LD 136
#define AGGH_SMEM ((128 * 120 + 112 * TS_LD) * 2)
__global__ void __launch_bounds__(256) k_aggh(const __half* __restrict__ T,
                                              const float* __restrict__ bias,
                                              __half* __restrict__ Hh) {
    extern __shared__ __half aggsh[];
    __half* Ash = aggsh;                   // [128][120]
    __half* Ts = aggsh + 128 * 120;        // [112][136]
    int gph = blockIdx.x;
    int cb = blockIdx.y * 128;
    int tid = threadIdx.x;
    int wid = tid >> 5, lane = tid & 31;
    int g = lane >> 2, q = lane & 3;
    int wm = wid >> 1, wn = wid & 1;

    const uint4* Asrc = (const uint4*)(d_Ah + (size_t)gph * 128 * 120);
    uint4* Adst = (uint4*)Ash;
    for (int i = tid; i < 128 * 120 / 8; i += 256) Adst[i] = Asrc[i];

    // Ts[k][n] direct copy: 16 x uint4 (=128 halves) per row, zero pad k 100..111
    const __half* Tg = T + (size_t)gph * NPG * HID + cb;
    const uint4 z4 = make_uint4(0, 0, 0, 0);
    for (int i = tid; i < 112 * 16; i += 256) {
        int k = i >> 4, c = i & 15;
        uint4 v = (k < NPG) ? *(const uint4*)(Tg + (size_t)k * HID + c * 8) : z4;
        *(uint4*)(Ts + k * TS_LD + c * 8) = v;
    }
    __syncthreads();

    uint32_t AshU = s2u(Ash), TsU = s2u(Ts);
    int laneA = (wm * 32 + (lane & 15)) * 120 + ((lane >> 4) & 1) * 8;
    int laneBt = (lane & 15) * TS_LD + wn * 64 + ((lane >> 4) & 1) * 8;

    float acc[2][8][4];
#pragma unroll
    for (int i = 0; i < 2; ++i)
#pragma unroll
        for (int j = 0; j < 8; ++j)
#pragma unroll
            for (int t = 0; t < 4; ++t) acc[i][j][t] = 0.f;

#pragma unroll
    for (int k0 = 0; k0 < 112; k0 += 16) {
        uint32_t af[2][4];
#pragma unroll
        for (int mi = 0; mi < 2; ++mi)
            ldm4(af[mi], AshU + (laneA + mi * 16 * 120 + k0) * 2);
#pragma unroll
        for (int p = 0; p < 4; ++p) {
            uint32_t bf[4];
            ldm4t(bf, TsU + (laneBt + k0 * TS_LD + p * 16) * 2);
#pragma unroll
            for (int mi = 0; mi < 2; ++mi) {
                mma_f16(acc[mi][2 * p], af[mi], bf);
                mma_f16(acc[mi][2 * p + 1], af[mi], bf + 2);
            }
        }
    }

#pragma unroll
    for (int mi = 0; mi < 2; ++mi) {
        int rl = wm * 32 + mi * 16 + g;
#pragma unroll
        for (int ni = 0; ni < 8; ++ni) {
            int col = cb + wn * 64 + ni * 8 + 2 * q;
            float2 bb = *(const float2*)(bias + col);
            if (rl < NPG) {
                size_t off = ((size_t)gph * NPG + rl) * HID + col;
                *(half2*)(Hh + off) =
                    __floats2half2_rn(acc[mi][ni][0] + bb.x, acc[mi][ni][1] + bb.y);
            }
            if (rl + 8 < NPG) {
                size_t off = ((size_t)gph * NPG + rl + 8) * HID + col;
                *(half2*)(Hh + off) =
                    __floats2half2_rn(acc[mi][ni][2] + bb.x, acc[mi][ni][3] + bb.y);
            }
        }
    }
}

// ---------------- fp32 tiled SGEMM (head only) ------------------------------
template <int EPI>
__global__ void sgemm(const float* __restrict__ A, const float* __restrict__ B,
                      const float* __restrict__ bias, float* __restrict__ C,
                      int M, int N, int K) {
    __shared__ float As[8][128];
    __shared__ float Bs[8][128];
    int tid = threadIdx.x;
    int m0 = blockIdx.y * 128;
    int n0 = blockIdx.x * 128;
    int arow = tid >> 1;
    int acol = (tid & 1) * 4;
    int brow = tid >> 5;
    int bcol = (tid & 31) * 4;
    int ty = tid >> 4;
    int tx = tid & 15;
    float acc[8][8] = {};

    for (int k0 = 0; k0 < K; k0 += 8) {
        float4 av = *(const float4*)(A + (size_t)(m0 + arow) * K + k0 + acol);
        As[acol + 0][arow] = av.x;
        As[acol + 1][arow] = av.y;
        As[acol + 2][arow] = av.z;
        As[acol + 3][arow] = av.w;
        *(float4*)(&Bs[brow][bcol]) =
            *(const float4*)(B + (size_t)(k0 + brow) * N + n0 + bcol);
        __syncthreads();
#pragma unroll
        for (int k = 0; k < 8; ++k) {
            float a[8], b[8];
            *(float4*)(a) = *(float4*)(&As[k][ty * 8]);
            *(float4*)(a + 4) = *(float4*)(&As[k][ty * 8 + 4]);
            *(float4*)(b) = *(float4*)(&Bs[k][tx * 8]);
            *(float4*)(b + 4) = *(float4*)(&Bs[k][tx * 8 + 4]);
#pragma unroll
            for (int i = 0; i < 8; ++i)
#pragma unroll
                for (int j = 0; j < 8; ++j) acc[i][j] = fmaf(a[i], b[j], acc[i][j]);
        }
        __syncthreads();
    }
#pragma unroll
    for (int i = 0; i < 8; ++i) {
        int row = m0 + ty * 8 + i;
#pragma unroll
        for (int j = 0; j < 8; j += 4) {
            int col = n0 + tx * 8 + j;
            float4 v = make_float4(acc[i][j], acc[i][j + 1], acc[i][j + 2], acc[i][j + 3]);
            if (EPI != 0) {
                float4 bb = *(const float4*)(bias + col);
                v.x += bb.x; v.y += bb.y; v.z += bb.z; v.w += bb.w;
                if (EPI == 1) {
                    v.x = tanhf(v.x); v.y = tanhf(v.y); v.z = tanhf(v.z); v.w = tanhf(v.w);
                } else {
                    v.x = fmaxf(v.x, 0.f); v.y = fmaxf(v.y, 0.f);
                    v.z = fmaxf(v.z, 0.f); v.w = fmaxf(v.w, 0.f);
                }
            }
            *(float4*)(C + (size_t)row * N + col) = v;
        }
    }
}

// ---------------- pos + assignment softmax + global h column sums -----------
__global__ void k_pos(const __half* __restrict__ H, const float* __restrict__ bc2) {
    __shared__ float a0[NPG];
    int g = blockIdx.x, c = threadIdx.x;   // 512 threads
    if (c < NPG) {
        int n = g * NPG + c;
        float z0 = d_araw[2 * n] + bc2[0], z1 = d_araw[2 * n + 1] + bc2[1];
        float m = fmaxf(z0, z1);
        float e0 = expf(z0 - m), e1 = expf(z1 - m);
        float inv = 1.f / (e0 + e1);
        float s0 = e0 * inv;
        a0[c] = s0;
        d_assign[2 * n] = s0;
        d_assign[2 * n + 1] = e1 * inv;
    }
    __syncthreads();
    const __half* h = H + (size_t)g * NPG * HID;
    float acc = 0.f, gs = 0.f;
    for (int n = 0; n < NPG; ++n) {
        float hv = __half2float(h[n * HID + c]);
        acc = fmaf(a0[n], hv, acc);
        gs += hv;
    }
    d_pos[g * HID + c] = acc;
    atomicAdd(&d_gvec[c], gs);
}

// ---------------- new_adj + penalty (fused, per-graph atomic) ---------------
__global__ void k_newadj(const int* __restrict__ ei) {
    __shared__ float sa[NPG * 2];
    __shared__ float red[4][4];
    int g = blockIdx.x, tid = threadIdx.x;
    if (tid < NPG * 2) sa[tid] = d_assign[g * NPG * 2 + tid];
    __syncthreads();
    float a00 = 0, a01 = 0, a10 = 0, a11 = 0;
    for (int e = tid; e < EPG; e += 128) {
        int s = ei[g * EPG + e] - g * NPG;
        int d = ei[N_EDGES + g * EPG + e] - g * NPG;
        float s0 = sa[2 * s], s1 = sa[2 * s + 1];
        float t0 = sa[2 * d], t1 = sa[2 * d + 1];
        a00 = fmaf(s0, t0, a00); a01 = fmaf(s0, t1, a01);
        a10 = fmaf(s1, t0, a10); a11 = fmaf(s1, t1, a11);
    }
#pragma unroll
    for (int o = 16; o > 0; o >>= 1) {
        a00 += __shfl_xor_sync(0xffffffff, a00, o);
        a01 += __shfl_xor_sync(0xffffffff, a01, o);
        a10 += __shfl_xor_sync(0xffffffff, a10, o);
        a11 += __shfl_xor_sync(0xffffffff, a11, o);
    }
    int warp = tid >> 5, lane = tid & 31;
    if (lane == 0) {
        red[warp][0] = a00; red[warp][1] = a01;
        red[warp][2] = a10; red[warp][3] = a11;
    }
    __syncthreads();
    if (tid == 0) {
        float v00 = red[0][0] + red[1][0] + red[2][0] + red[3][0];
        float v01 = red[0][1] + red[1][1] + red[2][1] + red[3][1];
        float v10 = red[0][2] + red[1][2] + red[2][2] + red[3][2];
        float v11 = red[0][3] + red[1][3] + red[2][3] + red[3][3];
        float r0 = fmaxf(fabsf(v00) + fabsf(v01), EPSV);
        float r1 = fmaxf(fabsf(v10) + fabsf(v11), EPSV);
        float dd0 = v00 / r0 - 1.f, dd1 = v11 / r1 - 1.f;
        atomicAdd(&d_scal[2], dd0 * dd0 + dd1 * dd1);
    }
}

// ---------------- merged norm reductions ------------------------------------
__global__ void k_norm() {
    __shared__ float red[256];
    int tid = threadIdx.x;
    if (blockIdx.x < 256) {
        float s = 0.f;
        for (int i = blockIdx.x * 256 + tid; i < NG * HID; i += 256 * 256) {
            float v = d_pos[i];
            s = fmaf(v, v, s);
        }
        red[tid] = s;
        __syncthreads();
        for (int o = 128; o > 0; o >>= 1) {
            if (tid < o) red[tid] += red[tid + o];
            __syncthreads();
        }
        if (tid == 0) atomicAdd(&d_scal[0], red[0]);
    } else {
        float v0 = d_gvec[tid] * (1.f / (float)N_NODES);
        float v1 = d_gvec[tid + 256] * (1.f / (float)N_NODES);
        red[tid] = v0 * v0 + v1 * v1;
        __syncthreads();
        for (int o = 128; o > 0; o >>= 1) {
            if (tid < o) red[tid] += red[tid + o];
            __syncthreads();
        }
        if (tid == 0) d_scal[1] = red[0] * (1.f / (float)HID);
    }
}

// ---------------- final outputs: pos, gemb, penalty -------------------------
__global__ void k_final(float* __restrict__ out) {
    int i = blockIdx.x * blockDim.x + threadIdx.x;
    if (i == 0) out[OUT_PEN] = d_scal[2] * (1.f / (NG * 2.f));
    if (i < NG * HID) {
        float ms = d_scal[0] * (1.f / (float)(NG * HID));
        float sc = (ms > 1.f) ? rsqrtf(ms) : 1.f;
        float v = d_pos[i] * sc;
        d_pos[i] = v;
        out[OUT_POS + i] = v;
        float ms2 = d_scal[1];
        float sc2 = (ms2 > 1.f) ? rsqrtf(ms2) : 1.f;
        out[OUT_GEMB + i] = d_gvec[i & (HID - 1)] * (1.f / (float)N_NODES) * sc2;
    }
}

// ---------------- head ------------------------------------------------------
__global__ void k_head(const float* __restrict__ Z, const float* __restrict__ Wl2,
                       const float* __restrict__ bl2, float* __restrict__ out) {
    __shared__ float w[HID * 6];
    int tid = threadIdx.x;
    for (int i = tid; i < HID * 6; i += 128) w[i] = Wl2[i];
    __syncthreads();
    int warp = tid >> 5, lane = tid & 31;
    int row = blockIdx.x * 4 + warp;
    const float* z = Z + (size_t)row * HID;
    float s[6] = {0, 0, 0, 0, 0, 0};
    for (int k = lane; k < HID; k += 32) {
        float zv = z[k];
#pragma unroll
        for (int j = 0; j < 6; ++j) s[j] = fmaf(zv, w[k * 6 + j], s[j]);
    }
#pragma unroll
    for (int o = 16; o > 0; o >>= 1)
#pragma unroll
        for (int j = 0; j < 6; ++j) s[j] += __shfl_xor_sync(0xffffffff, s[j], o);
    if (lane == 0) {
        float o6[6], m = -1e30f;
#pragma unroll
        for (int j = 0; j < 6; ++j) { o6[j] = s[j] + bl2[j]; m = fmaxf(m, o6[j]); }
        float sum = 0.f;
#pragma unroll
        for (int j = 0; j < 6; ++j) sum += expf(o6[j] - m);
        float lse = m + logf(sum);
#pragma unroll
        for (int j = 0; j < 6; ++j) out[OUT_LOGP + row * 6 + j] = o6[j] - lse;
    }
}

// ---------------- launch ----------------------------------------------------
extern "C" void kernel_launch(void* const* d_in, const int* in_sizes, int n_in,
                              void* d_out, int out_size) {
    const float* x   = (const float*)d_in[0];
    const int*   ei  = (const int*)d_in[1];
    const float* W1  = (const float*)d_in[4];
    const float* b1  = (const float*)d_in[5];
    const float* W2  = (const float*)d_in[6];
    const float* b2  = (const float*)d_in[7];
    const float* W3  = (const float*)d_in[8];
    const float* b3  = (const float*)d_in[9];
    const float* Wc1 = (const float*)d_in[10];
    const float* bc1 = (const float*)d_in[11];
    const float* Wc2 = (const float*)d_in[12];
    const float* bc2 = (const float*)d_in[13];
    const float* Wl1 = (const float*)d_in[14];
    const float* bl1 = (const float*)d_in[15];
    const float* Wl2 = (const float*)d_in[16];
    const float* bl2 = (const float*)d_in[17];
    float* out = (float*)d_out;

    float *pT, *pPos;
    __half *pTh, *pHh, *pXh, *pWh;
    cudaGetSymbolAddress((void**)&pT, d_T);
    cudaGetSymbolAddress((void**)&pPos, d_pos);
    cudaGetSymbolAddress((void**)&pTh, d_Th);
    cudaGetSymbolAddress((void**)&pHh, d_Hh);
    cudaGetSymbolAddress((void**)&pXh, d_Xh);
    cudaGetSymbolAddress((void**)&pWh, d_Wh);

    cudaFuncSetAttribute(k_aggh, cudaFuncAttributeMaxDynamicSharedMemorySize, AGGH_SMEM);
    cudaFuncSetAttribute(hgemm<FIN, 0>, cudaFuncAttributeMaxDynamicSharedMemorySize, HG_SMEM);
    cudaFuncSetAttribute(hgemm<HID, 0>, cudaFuncAttributeMaxDynamicSharedMemorySize, HG_SMEM);
    cudaFuncSetAttribute(hgemm<HID, 2>, cudaFuncAttributeMaxDynamicSharedMemorySize, HG_SMEM);

    __half* Wh0 = pWh;
    __half* Wh1 = pWh + HID * HID;
    __half* Wh2 = pWh + 2 * HID * HID;
    __half* Wh3 = pWh + 3 * HID * HID;

    // prep: zero, graph build, transposes + x->half (fused)
    k_zero_misc<<<100, 1024>>>();
    k_build<<<NG, 256>>>(ei);
    k_prep<<<dim3(16, 16, 5), dim3(32, 8)>>>(W1, W2, W3, Wc1, (const float4*)x);

    dim3 gBig(HID / 128, N_NODES / 128);
    dim3 gAgg(NG, 4);

    // 3 GCN layers: T = H@W (fp16 tensor) ; H = A_hat @ T + b (fp16 tensor)
    hgemm<FIN, 0><<<gBig, 256, HG_SMEM>>>(pXh, Wh0, nullptr, pTh, nullptr);
    k_aggh<<<gAgg, 256, AGGH_SMEM>>>(pTh, b1, pHh);
    hgemm<HID, 0><<<gBig, 256, HG_SMEM>>>(pHh, Wh1, nullptr, pTh, nullptr);
    k_aggh<<<gAgg, 256, AGGH_SMEM>>>(pTh, b2, pHh);
    hgemm<HID, 0><<<gBig, 256, HG_SMEM>>>(pHh, Wh2, nullptr, pTh, nullptr);
    k_aggh<<<gAgg, 256, AGGH_SMEM>>>(pTh, b3, pHh);

    // assignment fused into 4th GEMM epilogue
    hgemm<HID, 2><<<gBig, 256, HG_SMEM>>>(pHh, Wh3, bc1, pTh, Wc2);

    // pooling (with fused assignment softmax) / penalty
    k_pos<<<NG, HID>>>(pHh, bc2);
    k_newadj<<<NG, 128>>>(ei);

    // normalizations + final outputs
    k_norm<<<257, 256>>>();
    k_final<<<1024, 256>>>(out);

    // head MLP on normalized pos (fp32)
    dim3 gHead(HID / 128, NG / 128);
    sgemm<2><<<gHead, 256>>>(pPos, Wl1, bl1, pT, NG, HID, HID);
    k_head<<<NG / 4, 128>>>(pT, Wl2, bl2, out);
}